// round 12
// baseline (speedup 1.0000x reference)
#include <cuda_runtime.h>
#include <cuda_bf16.h>
#include <math.h>
#include <stdint.h>

#define CB 16
#define CN 512
#define CD 256
#define CH 8
#define CDFF 1024
#define CL 2
#define NEG_INF_F (-1e9f)

// ---------------- scratch (dedup'd split tensors: 2 physical segments) ----------------
static __device__ __align__(256) float g_x  [CB*CN*CD];
static __device__ __align__(256) float g_h  [CB*CN*CD];
static __device__ __align__(256) float g_qkv[CB*CN*768];
static __device__ __align__(256) float g_t  [CB*CN*CD];
static __device__ __align__(256) float g_ff [CB*CN*CDFF];
static __device__ __align__(256) float g_e1 [CB*CN];
static __device__ __align__(256) float g_e2 [CB*CN];
static __device__ __align__(256) float g_bias[CL*768];

static __device__ __align__(256) __nv_bfloat16 g_x3  [CB*CN*512];
static __device__ __align__(256) __nv_bfloat16 g_o3  [CB*CN*512];
static __device__ __align__(256) __nv_bfloat16 g_ff3 [CB*CN*2048];
static __device__ __align__(256) __nv_bfloat16 g_h3t [CB*CD*1024];
static __device__ __align__(256) __nv_bfloat16 g_al3 [CB*CN*1024];
static __device__ __align__(256) __nv_bfloat16 g_q3  [CB*CH*CN*128];
static __device__ __align__(256) __nv_bfloat16 g_k3  [CB*CH*CN*128];
static __device__ __align__(256) __nv_bfloat16 g_v3t [CB*CH*32*1024];
static __device__ __align__(256) __nv_bfloat16 g_wg3 [CD*512];
static __device__ __align__(256) __nv_bfloat16 g_wqkv3[CL*768*512];
static __device__ __align__(256) __nv_bfloat16 g_wo3 [CL*CD*512];
static __device__ __align__(256) __nv_bfloat16 g_w13 [CL*CDFF*512];
static __device__ __align__(256) __nv_bfloat16 g_w23 [CL*CD*2048];

__device__ __forceinline__ __nv_bfloat16 bf_lo(float v) {
    __nv_bfloat16 h = __float2bfloat16(v);
    return __float2bfloat16(v - __bfloat162float(h));
}
__device__ __forceinline__ void cpa16(uint32_t s, const void* g) {
    asm volatile("cp.async.cg.shared.global [%0], [%1], 16;" :: "r"(s), "l"(g));
}
__device__ __forceinline__ void ldsm4(uint32_t& r0, uint32_t& r1, uint32_t& r2, uint32_t& r3, uint32_t addr) {
    asm volatile("ldmatrix.sync.aligned.m8n8.x4.shared.b16 {%0,%1,%2,%3}, [%4];"
                 : "=r"(r0), "=r"(r1), "=r"(r2), "=r"(r3) : "r"(addr));
}
#define MMA16816(acc, a, b) \
    asm volatile("mma.sync.aligned.m16n8k16.row.col.f32.bf16.bf16.f32 " \
                 "{%0,%1,%2,%3}, {%4,%5,%6,%7}, {%8,%9}, {%0,%1,%2,%3};" \
                 : "+f"((acc)[0]), "+f"((acc)[1]), "+f"((acc)[2]), "+f"((acc)[3]) \
                 : "r"((a)[0]), "r"((a)[1]), "r"((a)[2]), "r"((a)[3]), \
                   "r"((b)[0]), "r"((b)[1]))

// ---------------- 3-stage cp.async mma.sync bf16 GEMM, chunk-remapped operands ----------------
template<int BM, int TN>
__global__ __launch_bounds__((BM/32)*(TN/32)*32)
void gemm_mma(const __nv_bfloat16* __restrict__ A, const __nv_bfloat16* __restrict__ B,
              const float* __restrict__ bias, float* __restrict__ C,
              int lda, int ldb, int ldc, int K3, int mapA, int mapB,
              long strA, long strB, long sC1, long sC2, int divC,
              float scale, int act,
              __nv_bfloat16* __restrict__ C3, long sC31, long sC32, int ldc3, int seg3)
{
    constexpr int WM = 32, WN = 32;
    constexpr int BK = 64;
    constexpr int LDS = BK + 8;
    constexpr int MT = 2, NT = 4;
    constexpr int WCOLS = TN / WN;
    constexpr int THREADS = (BM / WM) * (TN / WN) * 32;
    constexpr int AITERS = BM * 8 / THREADS;
    constexpr int BITERS = TN * 8 / THREADS;
    constexpr int STAGES = 3;

    extern __shared__ __nv_bfloat16 smem[];
    __nv_bfloat16* sA = smem;
    __nv_bfloat16* sB = smem + STAGES * BM * LDS;

    const long z = blockIdx.z;
    A += z * strA;
    B += z * strB;
    C += (z / divC) * sC1 + (z % divC) * sC2;
    if (C3) C3 += (z / divC) * sC31 + (z % divC) * sC32;
    const int row0 = blockIdx.y * BM;
    const int col0 = blockIdx.x * TN;

    const int tid = threadIdx.x;
    const int w = tid >> 5, lane = tid & 31;
    const int wr = w / WCOLS, wc = w % WCOLS;
    const int gid = lane >> 2, tig = lane & 3;

    uint32_t sAu = (uint32_t)__cvta_generic_to_shared(sA);
    uint32_t sBu = (uint32_t)__cvta_generic_to_shared(sB);

    const int aRow = lane & 15, aCol = (lane >> 4) << 3;
    const int bRow = ((lane >> 4) << 3) + (lane & 7), bCol = ((lane >> 3) & 1) << 3;

    float acc[MT][NT][4];
#pragma unroll
    for (int mt = 0; mt < MT; mt++)
#pragma unroll
        for (int nt = 0; nt < NT; nt++)
#pragma unroll
            for (int i = 0; i < 4; i++) acc[mt][nt][i] = 0.f;

    const int nChunks = K3 / BK;

    auto issue = [&](int s) {
        const int buf = s % STAGES;
        const int k0 = s * BK;
        const int k0a = mapA ? (k0 < 2 * mapA ? k0 : k0 - 2 * mapA) : k0;
        const int k0b = mapB ? (k0 < mapB ? k0 : k0 - mapB) : k0;
#pragma unroll
        for (int i = 0; i < AITERS; i++) {
            const int idx = i * THREADS + tid;
            const int r = idx >> 3, kc = (idx & 7) * 8;
            cpa16(sAu + (uint32_t)(((buf * BM + r) * LDS + kc) * 2),
                  A + (long)(row0 + r) * lda + k0a + kc);
        }
#pragma unroll
        for (int i = 0; i < BITERS; i++) {
            const int idx = i * THREADS + tid;
            const int r = idx >> 3, kc = (idx & 7) * 8;
            cpa16(sBu + (uint32_t)(((buf * TN + r) * LDS + kc) * 2),
                  B + (long)(col0 + r) * ldb + k0b + kc);
        }
        asm volatile("cp.async.commit_group;");
    };

    issue(0);
    if (nChunks > 1) issue(1);
    for (int c = 0; c < nChunks; c++) {
        if (c + 2 < nChunks) issue(c + 2);
        const int rem = nChunks - 1 - c;
        if (rem >= 2)      asm volatile("cp.async.wait_group 2;");
        else if (rem == 1) asm volatile("cp.async.wait_group 1;");
        else               asm volatile("cp.async.wait_group 0;");
        __syncthreads();

        const int buf = c % STAGES;
        const uint32_t aBase = sAu + (uint32_t)(buf * BM * LDS * 2);
        const uint32_t bBase = sBu + (uint32_t)(buf * TN * LDS * 2);
#pragma unroll
        for (int kk = 0; kk < BK; kk += 16) {
            uint32_t af[MT][4], bfr[NT][2];
#pragma unroll
            for (int mt = 0; mt < MT; mt++) {
                const int r = wr * WM + mt * 16;
                ldsm4(af[mt][0], af[mt][1], af[mt][2], af[mt][3],
                      aBase + (uint32_t)(((r + aRow) * LDS + kk + aCol) * 2));
            }
#pragma unroll
            for (int nt = 0; nt < NT; nt += 2) {
                const int n0 = wc * WN + nt * 8;
                ldsm4(bfr[nt][0], bfr[nt][1], bfr[nt + 1][0], bfr[nt + 1][1],
                      bBase + (uint32_t)(((n0 + bRow) * LDS + kk + bCol) * 2));
            }
#pragma unroll
            for (int mt = 0; mt < MT; mt++)
#pragma unroll
                for (int nt = 0; nt < NT; nt++)
                    MMA16816(acc[mt][nt], af[mt], bfr[nt]);
        }
        __syncthreads();
    }

    // epilogue
#pragma unroll
    for (int mt = 0; mt < MT; mt++) {
#pragma unroll
        for (int nt = 0; nt < NT; nt++) {
            const int rloc = wr * WM + mt * 16 + gid;
            const int cloc = wc * WN + nt * 8 + tig * 2;
            const int cg = col0 + cloc;
            float b0 = bias ? bias[cg] : 0.f;
            float b1 = bias ? bias[cg + 1] : 0.f;
#pragma unroll
            for (int half = 0; half < 2; half++) {
                const int rg = row0 + rloc + half * 8;
                float v0 = acc[mt][nt][half * 2 + 0] * scale + b0;
                float v1 = acc[mt][nt][half * 2 + 1] * scale + b1;
                if (act == 1) { v0 = fmaxf(v0, 0.f); v1 = fmaxf(v1, 0.f); }
                else if (act == 2) {
                    v0 = (v0 > 0.f) ? v0 : expm1f(v0);
                    v1 = (v1 > 0.f) ? v1 : expm1f(v1);
                }
                *reinterpret_cast<float2*>(&C[(long)rg * ldc + cg]) = make_float2(v0, v1);
                if (C3) {
                    long base = (long)rg * ldc3 + cg;
                    *reinterpret_cast<__nv_bfloat162*>(&C3[base]) =
                        __nv_bfloat162(__float2bfloat16(v0), __float2bfloat16(v1));
                    *reinterpret_cast<__nv_bfloat162*>(&C3[base + seg3]) =
                        __nv_bfloat162(bf_lo(v0), bf_lo(v1));
                }
            }
        }
    }
}

// ---------------- fused softmax + attn@v ----------------
// Block: 128 thr (4 warps), 64 q-rows, one (b,h). Output o3 [hi|lo] only.
__global__ __launch_bounds__(128)
void softmax_av(float* __restrict__ s, const int* __restrict__ mask,
                const __nv_bfloat16* __restrict__ v3t,
                __nv_bfloat16* __restrict__ o3, int writeProbs)
{
    constexpr int LDA = 136;   // pbuf row stride (128+8)
    constexpr int LDB = 1032;  // vbuf row stride (1024+8)
    extern __shared__ __nv_bfloat16 dsm[];
    __nv_bfloat16* vbuf = dsm;                 // [32][LDB]
    __nv_bfloat16* pbuf = dsm + 32 * LDB;      // [64][LDA]
    __shared__ float rowm[64], rowinv[64];

    const int z = blockIdx.z;
    const int q0 = blockIdx.x * 64;
    const int mb = (z >> 3) * CN;
    float* sbase = s + (long)z * CN * CN;
    const __nv_bfloat16* vb = v3t + (long)z * 32 * 1024;
    o3 += (long)(z >> 3) * ((long)CN * 512) + (z & 7) * 32;

    const int tid = threadIdx.x;
    const int w = tid >> 5, lane = tid & 31;
    const int gid = lane >> 2, tig = lane & 3;

    uint32_t vbu = (uint32_t)__cvta_generic_to_shared(vbuf);
    uint32_t pbu = (uint32_t)__cvta_generic_to_shared(pbuf);

    // async load whole v tile for this head: 32 rows x 1024 bf16
#pragma unroll
    for (int i = 0; i < 32; i++) {
        const int idx = i * 128 + tid;
        const int r = idx >> 7, ch = idx & 127;
        cpa16(vbu + (uint32_t)((r * LDB + ch * 8) * 2), vb + r * 1024 + ch * 8);
    }
    asm volatile("cp.async.commit_group;");

    // pass 1: per-row max and sum (warp w owns rows w*16..w*16+15)
    for (int i = 0; i < 16; i++) {
        const int r = w * 16 + i;
        const float* srow = sbase + (long)(q0 + r) * CN;
        float mx = -1e30f;
        for (int j = lane; j < CN; j += 32)
            mx = fmaxf(mx, srow[j] + (float)mask[mb + j] * NEG_INF_F);
#pragma unroll
        for (int off = 16; off > 0; off >>= 1)
            mx = fmaxf(mx, __shfl_xor_sync(0xffffffffu, mx, off));
        float sum = 0.f;
        for (int j = lane; j < CN; j += 32)
            sum += __expf(srow[j] + (float)mask[mb + j] * NEG_INF_F - mx);
#pragma unroll
        for (int off = 16; off > 0; off >>= 1)
            sum += __shfl_xor_sync(0xffffffffu, sum, off);
        if (lane == 0) { rowm[r] = mx; rowinv[r] = 1.f / sum; }
    }
    asm volatile("cp.async.wait_group 0;");
    __syncthreads();

    const int aRow = lane & 15, aCol = (lane >> 4) << 3;
    const int bRow = ((lane >> 4) << 3) + (lane & 7), bCol = ((lane >> 3) & 1) << 3;

    float acc[4][4];
#pragma unroll
    for (int nt = 0; nt < 4; nt++)
#pragma unroll
        for (int i = 0; i < 4; i++) acc[nt][i] = 0.f;

    for (int jc = 0; jc < 8; jc++) {
        // fill warp-private pbuf rows with normalized probs (hi | lo)
#pragma unroll
        for (int i = 0; i < 16; i++) {
            const int r = w * 16 + i;
            const int j = jc * 64 + lane * 2;
            float* sp = sbase + (long)(q0 + r) * CN + j;
            float2 v2 = *reinterpret_cast<const float2*>(sp);
            const float m = rowm[r], inv = rowinv[r];
            float p0 = __expf(v2.x + (float)mask[mb + j] * NEG_INF_F - m) * inv;
            float p1 = __expf(v2.y + (float)mask[mb + j + 1] * NEG_INF_F - m) * inv;
            if (writeProbs) *reinterpret_cast<float2*>(sp) = make_float2(p0, p1);
            *reinterpret_cast<__nv_bfloat162*>(&pbuf[r * LDA + lane * 2]) =
                __nv_bfloat162(__float2bfloat16(p0), __float2bfloat16(p1));
            *reinterpret_cast<__nv_bfloat162*>(&pbuf[r * LDA + 64 + lane * 2]) =
                __nv_bfloat162(bf_lo(p0), bf_lo(p1));
        }
        __syncwarp();
        const int koffA[3] = {0, 64, 0};
        const int coffB[3] = {jc * 64, jc * 64, 512 + jc * 64};
#pragma unroll
        for (int t3 = 0; t3 < 3; t3++) {
#pragma unroll
            for (int kk = 0; kk < 64; kk += 16) {
                uint32_t af[4];
                ldsm4(af[0], af[1], af[2], af[3],
                      pbu + (uint32_t)(((w * 16 + aRow) * LDA + koffA[t3] + kk + aCol) * 2));
                uint32_t bfr[4][2];
#pragma unroll
                for (int nt = 0; nt < 4; nt += 2) {
                    const int n0 = nt * 8;
                    ldsm4(bfr[nt][0], bfr[nt][1], bfr[nt + 1][0], bfr[nt + 1][1],
                          vbu + (uint32_t)(((n0 + bRow) * LDB + coffB[t3] + kk + bCol) * 2));
                }
#pragma unroll
                for (int nt = 0; nt < 4; nt++)
                    MMA16816(acc[nt], af, bfr[nt]);
            }
        }
        __syncwarp();
    }

    // epilogue: o3 only ([hi|lo], ld 512, seg 256)
#pragma unroll
    for (int nt = 0; nt < 4; nt++) {
        const int cg = nt * 8 + tig * 2;
#pragma unroll
        for (int half = 0; half < 2; half++) {
            const int rg = q0 + w * 16 + gid + half * 8;
            const float v0 = acc[nt][half * 2 + 0];
            const float v1 = acc[nt][half * 2 + 1];
            const long base = (long)rg * 512 + cg;
            *reinterpret_cast<__nv_bfloat162*>(&o3[base]) =
                __nv_bfloat162(__float2bfloat16(v0), __float2bfloat16(v1));
            *reinterpret_cast<__nv_bfloat162*>(&o3[base + 256]) =
                __nv_bfloat162(bf_lo(v0), bf_lo(v1));
        }
    }
}

// ---------------- fused weight split ----------------
struct WEnt { const float* src; __nv_bfloat16* dst; int R; int C; int tiles; };
struct WTab { WEnt e[13]; };

__global__ void wsplit_all(WTab tab)
{
    __shared__ float tile[128][33];
    int bid = blockIdx.x;
    int i = 0;
    while (bid >= tab.e[i].tiles) { bid -= tab.e[i].tiles; i++; }
    const float* in = tab.e[i].src;
    __nv_bfloat16* out = tab.e[i].dst;
    const int R = tab.e[i].R, C = tab.e[i].C;
    const int tC = C >> 5;
    const int r0 = (bid / tC) * 128, c0 = (bid % tC) * 32;

    for (int t = threadIdx.x; t < 128 * 32; t += 256) {
        int rr = t >> 5, cc = t & 31;
        tile[rr][cc] = in[(long)(r0 + rr) * C + c0 + cc];
    }
    __syncthreads();
    for (int t = threadIdx.x; t < 32 * 128; t += 256) {
        int cc = t >> 7, rr = t & 127;
        float v = tile[rr][cc];
        long ob = (long)(c0 + cc) * (2L * R) + (r0 + rr);
        out[ob] = __float2bfloat16(v);
        out[ob + R] = bf_lo(v);
    }
}

__global__ void pack_bias(const float* __restrict__ bq, const float* __restrict__ bk,
                          const float* __restrict__ bv, float* __restrict__ dst)
{
    const int l = blockIdx.x;
    const int d = threadIdx.x;
    float v;
    if (d < 256) v = bq[l * 256 + d];
    else if (d < 512) v = bk[l * 256 + d - 256];
    else v = bv[l * 256 + d - 512];
    dst[l * 768 + d] = v;
}

// ---------------- elementwise kernels ----------------

__global__ void embed_kernel(const int* __restrict__ node, const float* __restrict__ embed,
                             float* __restrict__ x, __nv_bfloat16* __restrict__ x3)
{
    const int row = blockIdx.x;
    const int d = threadIdx.x;
    const float v = embed[(long)node[row] * CD + d];
    x[(long)row * CD + d] = v;
    x3[(long)row * 512 + d] = __float2bfloat16(v);
    x3[(long)row * 512 + 256 + d] = bf_lo(v);
}

__global__ void tsplitB(const float* __restrict__ in, __nv_bfloat16* __restrict__ out,
                        int irs, int R, long sIn1, long sIn2, int divIn, long sOut)
{
    __shared__ float tile[128][33];
    const long z = blockIdx.z;
    in  += (z / divIn) * sIn1 + (z % divIn) * sIn2;
    out += z * sOut;
    const int r0 = blockIdx.x * 128, c0 = blockIdx.y * 32;
    for (int i = threadIdx.x; i < 128 * 32; i += 256) {
        int rr = i >> 5, cc = i & 31;
        tile[rr][cc] = in[(long)(r0 + rr) * irs + c0 + cc];
    }
    __syncthreads();
    for (int i = threadIdx.x; i < 32 * 128; i += 256) {
        int cc = i >> 7, rr = i & 127;
        float v = tile[rr][cc];
        long ob = (long)(c0 + cc) * (2L * R) + (r0 + rr);
        out[ob] = __float2bfloat16(v);
        out[ob + R] = bf_lo(v);
    }
}

__global__ void qk_split(const float* __restrict__ qkv,
                         __nv_bfloat16* __restrict__ q3, __nv_bfloat16* __restrict__ k3)
{
    const int row = blockIdx.x;
    const int b = row >> 9, i = row & 511;
    const int d = threadIdx.x;
    const int h = d >> 5, dd = d & 31;
    const long base = ((long)(b * CH + h) * CN + i) * 128;
    const __nv_bfloat16 zero = __float2bfloat16(0.f);
    float qv = qkv[(long)row * 768 + d];
    float kv = qkv[(long)row * 768 + 256 + d];
    __nv_bfloat16 qh = __float2bfloat16(qv);
    __nv_bfloat16 ql = bf_lo(qv);
    __nv_bfloat16 kh = __float2bfloat16(kv);
    __nv_bfloat16 kl = bf_lo(kv);
    q3[base + dd] = qh;  q3[base + 32 + dd] = ql; q3[base + 64 + dd] = qh; q3[base + 96 + dd] = zero;
    k3[base + dd] = kh;  k3[base + 32 + dd] = kh; k3[base + 64 + dd] = kl; k3[base + 96 + dd] = zero;
}

__global__ void e12_kernel(const float* __restrict__ h, const float* __restrict__ a1,
                           const float* __restrict__ a2, float* __restrict__ e1, float* __restrict__ e2)
{
    const int row = blockIdx.x;
    const int d = threadIdx.x;
    __shared__ float s1[256], s2[256];
    const float hv = h[(long)row * CD + d];
    s1[d] = hv * a1[d];
    s2[d] = hv * a2[d];
    __syncthreads();
    for (int off = 128; off > 0; off >>= 1) {
        if (d < off) { s1[d] += s1[d + off]; s2[d] += s2[d + off]; }
        __syncthreads();
    }
    if (d == 0) { e1[row] = s1[0]; e2[row] = s2[0]; }
}

__global__ void gat_softmax_kernel(const float* __restrict__ e1, const float* __restrict__ e2,
                                   const int* __restrict__ edge, __nv_bfloat16* __restrict__ al3)
{
    const int row = blockIdx.x;
    const int b = row / CN;
    const int t = threadIdx.x;
    __shared__ float red[256];
    const float ei = e1[row];
    float vals[2];
#pragma unroll
    for (int p = 0; p < 2; p++) {
        const int j = t + p * 256;
        float e = ei + e2[b * CN + j];
        e = (e >= 0.f) ? e : 0.2f * e;
        vals[p] = (edge[(long)row * CN + j] > 0) ? e : NEG_INF_F;
    }
    red[t] = fmaxf(vals[0], vals[1]);
    __syncthreads();
    for (int off = 128; off > 0; off >>= 1) { if (t < off) red[t] = fmaxf(red[t], red[t + off]); __syncthreads(); }
    const float m = red[0];
    __syncthreads();
    float ex[2] = {__expf(vals[0] - m), __expf(vals[1] - m)};
    red[t] = ex[0] + ex[1];
    __syncthreads();
    for (int off = 128; off > 0; off >>= 1) { if (t < off) red[t] += red[t + off]; __syncthreads(); }
    const float inv = 1.f / red[0];
    const long b3 = (long)row * 1024;
#pragma unroll
    for (int p = 0; p < 2; p++) {
        const int j = t + p * 256;
        const float pr = ex[p] * inv;
        al3[b3 + j] = __float2bfloat16(pr);
        al3[b3 + 512 + j] = bf_lo(pr);
    }
}

__global__ void scale_pe_kernel(float* __restrict__ x, __nv_bfloat16* __restrict__ x3)
{
    const int row = blockIdx.x;
    const int n = row % CN;
    const int d = threadIdx.x;
    const float expo = (2.0f * (float)(d >> 1)) / (float)CD;
    const float angle = (float)n * powf(10000.0f, -expo);
    const float pe = (d & 1) ? cosf(angle) : sinf(angle);
    const long idx = (long)row * CD + d;
    const float v = x[idx] * 16.0f + pe;
    x[idx] = v;
    x3[(long)row * 512 + d] = __float2bfloat16(v);
    x3[(long)row * 512 + 256 + d] = bf_lo(v);
}

__global__ void ln_kernel(const float* __restrict__ x, const float* __restrict__ delta,
                          const float* __restrict__ g, const float* __restrict__ bb,
                          float* __restrict__ out, __nv_bfloat16* __restrict__ x3)
{
    const int row = blockIdx.x;
    const int d = threadIdx.x;
    __shared__ float red[256];
    const long idx = (long)row * CD + d;
    const float v = x[idx] + delta[idx];
    red[d] = v;
    __syncthreads();
    for (int off = 128; off > 0; off >>= 1) { if (d < off) red[d] += red[d + off]; __syncthreads(); }
    const float mu = red[0] * (1.0f / CD);
    __syncthreads();
    const float c = v - mu;
    red[d] = c * c;
    __syncthreads();
    for (int off = 128; off > 0; off >>= 1) { if (d < off) red[d] += red[d + off]; __syncthreads(); }
    const float var = red[0] * (1.0f / CD);
    const float r = c * rsqrtf(var + 1e-6f) * g[d] + bb[d];
    out[idx] = r;
    if (x3) {
        x3[(long)row * 512 + d] = __float2bfloat16(r);
        x3[(long)row * 512 + 256 + d] = bf_lo(r);
    }
}

// ---------------- host ----------------
struct G3 { __nv_bfloat16* p; long s1; long s2; int ld; int seg; };

static void launch_gemm(const __nv_bfloat16* A, const __nv_bfloat16* B, const float* bias, float* C,
                        int M, int N, int K3, int lda, int ldb, int ldc, int mapA, int mapB,
                        long sA, long sB, long sC1, long sC2, int divC,
                        float scale, int act, int batch, G3 g3)
{
    dim3 g(N / 64, M / 64, batch);
    size_t sm = 3 * (64 + 64) * 72 * 2;
    gemm_mma<64, 64><<<g, 128, sm>>>(A, B, bias, C, lda, ldb, ldc, K3, mapA, mapB,
        sA, sB, sC1, sC2, divC, scale, act, g3.p, g3.s1, g3.s2, g3.ld, g3.seg);
}

extern "C" void kernel_launch(void* const* d_in, const int* in_sizes, int n_in,
                              void* d_out, int out_size)
{
    const int*   node  = (const int*)  d_in[0];
    const int*   edge  = (const int*)  d_in[1];
    const int*   mask  = (const int*)  d_in[2];
    const float* embed = (const float*)d_in[4];
    const float* Wg    = (const float*)d_in[5];
    const float* a1    = (const float*)d_in[6];
    const float* a2    = (const float*)d_in[7];
    const float* Wq    = (const float*)d_in[8];
    const float* bq    = (const float*)d_in[9];
    const float* Wk    = (const float*)d_in[10];
    const float* bk    = (const float*)d_in[11];
    const float* Wv    = (const float*)d_in[12];
    const float* bv    = (const float*)d_in[13];
    const float* Wo    = (const float*)d_in[14];
    const float* bo    = (const float*)d_in[15];
    const float* W1    = (const float*)d_in[16];
    const float* b1    = (const float*)d_in[17];
    const float* W2    = (const float*)d_in[18];
    const float* b2    = (const float*)d_in[19];
    const float* ln1g  = (const float*)d_in[20];
    const float* ln1b  = (const float*)d_in[21];
    const float* ln2g  = (const float*)d_in[22];
    const float* ln2b  = (const float*)d_in[23];

    cudaFuncSetAttribute((const void*)gemm_mma<64,64>, cudaFuncAttributeMaxDynamicSharedMemorySize, 60000);
    cudaFuncSetAttribute((const void*)softmax_av, cudaFuncAttributeMaxDynamicSharedMemorySize, 90000);

    float *x, *h, *qkv, *t, *ff, *e1, *e2, *bias3;
    __nv_bfloat16 *x3, *o3, *ff3, *h3t, *al3, *q3, *k3, *v3t;
    __nv_bfloat16 *wg3, *wqkv3, *wo3, *w13, *w23;
    cudaGetSymbolAddress((void**)&x, g_x);     cudaGetSymbolAddress((void**)&h, g_h);
    cudaGetSymbolAddress((void**)&qkv, g_qkv); cudaGetSymbolAddress((void**)&t, g_t);
    cudaGetSymbolAddress((void**)&ff, g_ff);
    cudaGetSymbolAddress((void**)&e1, g_e1);   cudaGetSymbolAddress((void**)&e2, g_e2);
    cudaGetSymbolAddress((void**)&bias3, g_bias);
    cudaGetSymbolAddress((void**)&x3, g_x3);   cudaGetSymbolAddress((void**)&o3, g_o3);
    cudaGetSymbolAddress((void**)&ff3, g_ff3); cudaGetSymbolAddress((void**)&h3t, g_h3t);
    cudaGetSymbolAddress((void**)&al3, g_al3);
    cudaGetSymbolAddress((void**)&q3, g_q3);   cudaGetSymbolAddress((void**)&k3, g_k3);
    cudaGetSymbolAddress((void**)&v3t, g_v3t);
    cudaGetSymbolAddress((void**)&wg3, g_wg3); cudaGetSymbolAddress((void**)&wqkv3, g_wqkv3);
    cudaGetSymbolAddress((void**)&wo3, g_wo3); cudaGetSymbolAddress((void**)&w13, g_w13);
    cudaGetSymbolAddress((void**)&w23, g_w23);

    float* out_x    = (float*)d_out;
    float* out_attn = (float*)d_out + (long)CB * CN * CD;

    const int M = CB * CN;
    const long ND = (long)CN * CD;
    const float inv_sqrt_dh = 0.17677669529663687f;
    const G3 no3 = {nullptr, 0, 0, 0, 0};

    WTab tab;
    int nTiles = 0;
    auto add = [&](int i, const float* src, __nv_bfloat16* dst, int R, int C) {
        tab.e[i] = {src, dst, R, C, (R / 128) * (C / 32)};
        nTiles += tab.e[i].tiles;
    };
    add(0, Wg, wg3, 256, 256);
    for (int l = 0; l < CL; l++) {
        const long w256 = (long)l * 65536, w1k = (long)l * 262144;
        add(1 + l * 6, Wq + w256, wqkv3 + (long)l * 768 * 512, 256, 256);
        add(2 + l * 6, Wk + w256, wqkv3 + (long)l * 768 * 512 + 256 * 512, 256, 256);
        add(3 + l * 6, Wv + w256, wqkv3 + (long)l * 768 * 512 + 512 * 512, 256, 256);
        add(4 + l * 6, Wo + w256, wo3 + (long)l * 256 * 512, 256, 256);
        add(5 + l * 6, W1 + w1k, w13 + (long)l * 1024 * 512, 256, 1024);
        add(6 + l * 6, W2 + w1k, w23 + (long)l * 256 * 2048, 1024, 256);
    }
    wsplit_all<<<nTiles, 256>>>(tab);
    pack_bias<<<CL, 768>>>(bq, bk, bv, bias3);

    embed_kernel<<<M, CD>>>(node, embed, x, x3);

    for (int hop = 0; hop < 2; hop++) {
        launch_gemm(x3, wg3, nullptr, h, M, CD, 768, 512, 512, CD, 256, 256,
                    0, 0, 0, 0, 1, 1.f, 0, 1, no3);
        tsplitB<<<dim3(4, 8, CB), 256>>>(h, h3t, CD, CN, ND, 0, 1, (long)CD * 1024);
        e12_kernel<<<M, CD>>>(h, a1, a2, e1, e2);
        gat_softmax_kernel<<<M, 256>>>(e1, e2, edge, al3);
        G3 gx3 = {x3, (long)CN * 512, 0, 512, 256};
        launch_gemm(al3, h3t, nullptr, x, CN, CD, 1536, 1024, 1024, CD, 512, 512,
                    (long)CN * 1024, (long)CD * 1024, ND, 0, 1, 1.f, 2, CB, gx3);
    }

    scale_pe_kernel<<<M, CD>>>(x, x3);

    for (int l = 0; l < CL; l++) {
        launch_gemm(x3, wqkv3 + (long)l * 768 * 512, bias3 + l * 768, qkv,
                    M, 768, 768, 512, 512, 768, 256, 256,
                    0, 0, 0, 0, 1, 1.f, 0, 1, no3);

        qk_split<<<M, 256>>>(qkv, q3, k3);
        tsplitB<<<dim3(4, 1, CB * CH), 256>>>(qkv + 512, v3t, 768, CN,
                                              (long)CN * 768, 32, CH, 32L * 1024);

        launch_gemm(q3, k3, nullptr, out_attn, CN, CN, 128, 128, 128, CN, 0, 0,
                    (long)CN * 128, (long)CN * 128, (long)CN * CN, 0, 1,
                    inv_sqrt_dh, 0, CB * CH, no3);

        // fused softmax + attn@v -> o3 (probs written in place only for last layer)
        softmax_av<<<dim3(8, 1, CB * CH), 128, (32 * 1032 + 64 * 136) * 2>>>(
            out_attn, mask, v3t, o3, l == CL - 1 ? 1 : 0);

        launch_gemm(o3, wo3 + (long)l * 256 * 512, bo + l * CD, t, M, CD, 768,
                    512, 512, CD, 256, 256,
                    0, 0, 0, 0, 1, 1.f, 0, 1, no3);
        ln_kernel<<<M, CD>>>(x, t, ln1g + l * CD, ln1b + l * CD, x, x3);

        G3 gff3 = {ff3, 0, 0, 2048, 1024};
        launch_gemm(x3, w13 + (long)l * 1024 * 512, b1 + l * CDFF, ff, M, CDFF, 768,
                    512, 512, CDFF, 256, 256,
                    0, 0, 0, 0, 1, 1.f, 1, 1, gff3);
        launch_gemm(ff3, w23 + (long)l * 256 * 2048, b2 + l * CD, t, M, CD, 3072,
                    2048, 2048, CD, 1024, 1024,
                    0, 0, 0, 0, 1, 1.f, 0, 1, no3);
        const bool last = (l == CL - 1);
        ln_kernel<<<M, CD>>>(x, t, ln2g + l * CD, ln2b + l * CD,
                             last ? out_x : x, last ? nullptr : x3);
    }
}

// round 13
// speedup vs baseline: 1.0195x; 1.0195x over previous
#include <cuda_runtime.h>
#include <cuda_bf16.h>
#include <math.h>
#include <stdint.h>

#define CB 16
#define CN 512
#define CD 256
#define CH 8
#define CDFF 1024
#define CL 2
#define NEG_INF_F (-1e9f)

// ---------------- scratch (dedup'd split tensors) ----------------
static __device__ __align__(256) float g_x  [CB*CN*CD];
static __device__ __align__(256) float g_h  [CB*CN*CD];
static __device__ __align__(256) float g_qkv[CB*CN*768];
static __device__ __align__(256) float g_t  [CB*CN*CD];
static __device__ __align__(256) float g_e1 [CB*CN];
static __device__ __align__(256) float g_e2 [CB*CN];
static __device__ __align__(256) float g_bias[CL*768];

static __device__ __align__(256) __nv_bfloat16 g_x3  [CB*CN*512];
static __device__ __align__(256) __nv_bfloat16 g_o3  [CB*CN*512];
static __device__ __align__(256) __nv_bfloat16 g_ff3 [CB*CN*2048];
static __device__ __align__(256) __nv_bfloat16 g_h3t [CB*CD*1024];
static __device__ __align__(256) __nv_bfloat16 g_al3 [CB*CN*1024];
static __device__ __align__(256) __nv_bfloat16 g_q3  [CB*CH*CN*64];
static __device__ __align__(256) __nv_bfloat16 g_k3  [CB*CH*CN*64];
static __device__ __align__(256) __nv_bfloat16 g_v3t [CB*CH*32*1024];
static __device__ __align__(256) __nv_bfloat16 g_wg3 [CD*512];
static __device__ __align__(256) __nv_bfloat16 g_wqkv3[CL*768*512];
static __device__ __align__(256) __nv_bfloat16 g_wo3 [CL*CD*512];
static __device__ __align__(256) __nv_bfloat16 g_w13 [CL*CDFF*512];
static __device__ __align__(256) __nv_bfloat16 g_w23 [CL*CD*2048];

__device__ __forceinline__ __nv_bfloat16 bf_lo(float v) {
    __nv_bfloat16 h = __float2bfloat16(v);
    return __float2bfloat16(v - __bfloat162float(h));
}
__device__ __forceinline__ void cpa16(uint32_t s, const void* g) {
    asm volatile("cp.async.cg.shared.global [%0], [%1], 16;" :: "r"(s), "l"(g));
}
__device__ __forceinline__ void ldsm4(uint32_t& r0, uint32_t& r1, uint32_t& r2, uint32_t& r3, uint32_t addr) {
    asm volatile("ldmatrix.sync.aligned.m8n8.x4.shared.b16 {%0,%1,%2,%3}, [%4];"
                 : "=r"(r0), "=r"(r1), "=r"(r2), "=r"(r3) : "r"(addr));
}
#define MMA16816(acc, a, b) \
    asm volatile("mma.sync.aligned.m16n8k16.row.col.f32.bf16.bf16.f32 " \
                 "{%0,%1,%2,%3}, {%4,%5,%6,%7}, {%8,%9}, {%0,%1,%2,%3};" \
                 : "+f"((acc)[0]), "+f"((acc)[1]), "+f"((acc)[2]), "+f"((acc)[3]) \
                 : "r"((a)[0]), "r"((a)[1]), "r"((a)[2]), "r"((a)[3]), \
                   "r"((b)[0]), "r"((b)[1]))

// ---------------- 3-stage cp.async mma.sync bf16 GEMM, chunk-remapped, C nullable ----------------
template<int BM, int TN, int BK>
__global__ __launch_bounds__((BM/32)*(TN/32)*32)
void gemm_mma(const __nv_bfloat16* __restrict__ A, const __nv_bfloat16* __restrict__ B,
              const float* __restrict__ bias, float* __restrict__ C,
              int lda, int ldb, int ldc, int K3, int mapA, int mapB,
              long strA, long strB, long sC1, long sC2, int divC,
              float scale, int act,
              __nv_bfloat16* __restrict__ C3, long sC31, long sC32, int ldc3, int seg3)
{
    constexpr int WM = 32, WN = 32;
    constexpr int LDS = BK + 8;
    constexpr int MT = 2, NT = 4;
    constexpr int WCOLS = TN / WN;
    constexpr int THREADS = (BM / WM) * (TN / WN) * 32;
    constexpr int AITERS = BM * (BK / 8) / THREADS;
    constexpr int BITERS = TN * (BK / 8) / THREADS;
    constexpr int STAGES = 3;

    extern __shared__ __nv_bfloat16 smem[];
    __nv_bfloat16* sA = smem;
    __nv_bfloat16* sB = smem + STAGES * BM * LDS;

    const long z = blockIdx.z;
    A += z * strA;
    B += z * strB;
    if (C)  C  += (z / divC) * sC1 + (z % divC) * sC2;
    if (C3) C3 += (z / divC) * sC31 + (z % divC) * sC32;
    const int row0 = blockIdx.y * BM;
    const int col0 = blockIdx.x * TN;

    const int tid = threadIdx.x;
    const int w = tid >> 5, lane = tid & 31;
    const int wr = w / WCOLS, wc = w % WCOLS;
    const int gid = lane >> 2, tig = lane & 3;

    uint32_t sAu = (uint32_t)__cvta_generic_to_shared(sA);
    uint32_t sBu = (uint32_t)__cvta_generic_to_shared(sB);

    const int aRow = lane & 15, aCol = (lane >> 4) << 3;
    const int bRow = ((lane >> 4) << 3) + (lane & 7), bCol = ((lane >> 3) & 1) << 3;

    float acc[MT][NT][4];
#pragma unroll
    for (int mt = 0; mt < MT; mt++)
#pragma unroll
        for (int nt = 0; nt < NT; nt++)
#pragma unroll
            for (int i = 0; i < 4; i++) acc[mt][nt][i] = 0.f;

    const int nChunks = K3 / BK;

    auto issue = [&](int s) {
        const int buf = s % STAGES;
        const int k0 = s * BK;
        const int k0a = mapA ? (k0 < 2 * mapA ? k0 : k0 - 2 * mapA) : k0;
        const int k0b = mapB ? (k0 < mapB ? k0 : k0 - mapB) : k0;
#pragma unroll
        for (int i = 0; i < AITERS; i++) {
            const int idx = i * THREADS + tid;
            const int r = idx / (BK / 8), kc = (idx % (BK / 8)) * 8;
            cpa16(sAu + (uint32_t)(((buf * BM + r) * LDS + kc) * 2),
                  A + (long)(row0 + r) * lda + k0a + kc);
        }
#pragma unroll
        for (int i = 0; i < BITERS; i++) {
            const int idx = i * THREADS + tid;
            const int r = idx / (BK / 8), kc = (idx % (BK / 8)) * 8;
            cpa16(sBu + (uint32_t)(((buf * TN + r) * LDS + kc) * 2),
                  B + (long)(col0 + r) * ldb + k0b + kc);
        }
        asm volatile("cp.async.commit_group;");
    };

    issue(0);
    if (nChunks > 1) issue(1);
    for (int c = 0; c < nChunks; c++) {
        if (c + 2 < nChunks) issue(c + 2);
        const int rem = nChunks - 1 - c;
        if (rem >= 2)      asm volatile("cp.async.wait_group 2;");
        else if (rem == 1) asm volatile("cp.async.wait_group 1;");
        else               asm volatile("cp.async.wait_group 0;");
        __syncthreads();

        const int buf = c % STAGES;
        const uint32_t aBase = sAu + (uint32_t)(buf * BM * LDS * 2);
        const uint32_t bBase = sBu + (uint32_t)(buf * TN * LDS * 2);
#pragma unroll
        for (int kk = 0; kk < BK; kk += 16) {
            uint32_t af[MT][4], bfr[NT][2];
#pragma unroll
            for (int mt = 0; mt < MT; mt++) {
                const int r = wr * WM + mt * 16;
                ldsm4(af[mt][0], af[mt][1], af[mt][2], af[mt][3],
                      aBase + (uint32_t)(((r + aRow) * LDS + kk + aCol) * 2));
            }
#pragma unroll
            for (int nt = 0; nt < NT; nt += 2) {
                const int n0 = wc * WN + nt * 8;
                ldsm4(bfr[nt][0], bfr[nt][1], bfr[nt + 1][0], bfr[nt + 1][1],
                      bBase + (uint32_t)(((n0 + bRow) * LDS + kk + bCol) * 2));
            }
#pragma unroll
            for (int mt = 0; mt < MT; mt++)
#pragma unroll
                for (int nt = 0; nt < NT; nt++)
                    MMA16816(acc[mt][nt], af[mt], bfr[nt]);
        }
        __syncthreads();
    }

    // epilogue
#pragma unroll
    for (int mt = 0; mt < MT; mt++) {
#pragma unroll
        for (int nt = 0; nt < NT; nt++) {
            const int rloc = wr * WM + mt * 16 + gid;
            const int cloc = wc * WN + nt * 8 + tig * 2;
            const int cg = col0 + cloc;
            float b0 = bias ? bias[cg] : 0.f;
            float b1 = bias ? bias[cg + 1] : 0.f;
#pragma unroll
            for (int half = 0; half < 2; half++) {
                const int rg = row0 + rloc + half * 8;
                float v0 = acc[mt][nt][half * 2 + 0] * scale + b0;
                float v1 = acc[mt][nt][half * 2 + 1] * scale + b1;
                if (act == 1) { v0 = fmaxf(v0, 0.f); v1 = fmaxf(v1, 0.f); }
                else if (act == 2) {
                    v0 = (v0 > 0.f) ? v0 : expm1f(v0);
                    v1 = (v1 > 0.f) ? v1 : expm1f(v1);
                }
                if (C)
                    *reinterpret_cast<float2*>(&C[(long)rg * ldc + cg]) = make_float2(v0, v1);
                if (C3) {
                    long base = (long)rg * ldc3 + cg;
                    *reinterpret_cast<__nv_bfloat162*>(&C3[base]) =
                        __nv_bfloat162(__float2bfloat16(v0), __float2bfloat16(v1));
                    *reinterpret_cast<__nv_bfloat162*>(&C3[base + seg3]) =
                        __nv_bfloat162(bf_lo(v0), bf_lo(v1));
                }
            }
        }
    }
}

// ---------------- fused softmax + attn@v ----------------
__global__ __launch_bounds__(128)
void softmax_av(float* __restrict__ s, const int* __restrict__ mask,
                const __nv_bfloat16* __restrict__ v3t,
                __nv_bfloat16* __restrict__ o3, int writeProbs)
{
    constexpr int LDA = 136;
    constexpr int LDB = 1032;
    extern __shared__ __nv_bfloat16 dsm[];
    __nv_bfloat16* vbuf = dsm;
    __nv_bfloat16* pbuf = dsm + 32 * LDB;
    __shared__ float rowm[64], rowinv[64];

    const int z = blockIdx.z;
    const int q0 = blockIdx.x * 64;
    const int mb = (z >> 3) * CN;
    float* sbase = s + (long)z * CN * CN;
    const __nv_bfloat16* vb = v3t + (long)z * 32 * 1024;
    o3 += (long)(z >> 3) * ((long)CN * 512) + (z & 7) * 32;

    const int tid = threadIdx.x;
    const int w = tid >> 5, lane = tid & 31;
    const int gid = lane >> 2, tig = lane & 3;

    uint32_t vbu = (uint32_t)__cvta_generic_to_shared(vbuf);
    uint32_t pbu = (uint32_t)__cvta_generic_to_shared(pbuf);

#pragma unroll
    for (int i = 0; i < 32; i++) {
        const int idx = i * 128 + tid;
        const int r = idx >> 7, ch = idx & 127;
        cpa16(vbu + (uint32_t)((r * LDB + ch * 8) * 2), vb + r * 1024 + ch * 8);
    }
    asm volatile("cp.async.commit_group;");

    for (int i = 0; i < 16; i++) {
        const int r = w * 16 + i;
        const float* srow = sbase + (long)(q0 + r) * CN;
        float mx = -1e30f;
        for (int j = lane; j < CN; j += 32)
            mx = fmaxf(mx, srow[j] + (float)mask[mb + j] * NEG_INF_F);
#pragma unroll
        for (int off = 16; off > 0; off >>= 1)
            mx = fmaxf(mx, __shfl_xor_sync(0xffffffffu, mx, off));
        float sum = 0.f;
        for (int j = lane; j < CN; j += 32)
            sum += __expf(srow[j] + (float)mask[mb + j] * NEG_INF_F - mx);
#pragma unroll
        for (int off = 16; off > 0; off >>= 1)
            sum += __shfl_xor_sync(0xffffffffu, sum, off);
        if (lane == 0) { rowm[r] = mx; rowinv[r] = 1.f / sum; }
    }
    asm volatile("cp.async.wait_group 0;");
    __syncthreads();

    const int aRow = lane & 15, aCol = (lane >> 4) << 3;
    const int bRow = ((lane >> 4) << 3) + (lane & 7), bCol = ((lane >> 3) & 1) << 3;

    float acc[4][4];
#pragma unroll
    for (int nt = 0; nt < 4; nt++)
#pragma unroll
        for (int i = 0; i < 4; i++) acc[nt][i] = 0.f;

    for (int jc = 0; jc < 8; jc++) {
#pragma unroll
        for (int i = 0; i < 16; i++) {
            const int r = w * 16 + i;
            const int j = jc * 64 + lane * 2;
            float* sp = sbase + (long)(q0 + r) * CN + j;
            float2 v2 = *reinterpret_cast<const float2*>(sp);
            const float m = rowm[r], inv = rowinv[r];
            float p0 = __expf(v2.x + (float)mask[mb + j] * NEG_INF_F - m) * inv;
            float p1 = __expf(v2.y + (float)mask[mb + j + 1] * NEG_INF_F - m) * inv;
            if (writeProbs) *reinterpret_cast<float2*>(sp) = make_float2(p0, p1);
            *reinterpret_cast<__nv_bfloat162*>(&pbuf[r * LDA + lane * 2]) =
                __nv_bfloat162(__float2bfloat16(p0), __float2bfloat16(p1));
            *reinterpret_cast<__nv_bfloat162*>(&pbuf[r * LDA + 64 + lane * 2]) =
                __nv_bfloat162(bf_lo(p0), bf_lo(p1));
        }
        __syncwarp();
        const int koffA[3] = {0, 64, 0};
        const int coffB[3] = {jc * 64, jc * 64, 512 + jc * 64};
#pragma unroll
        for (int t3 = 0; t3 < 3; t3++) {
#pragma unroll
            for (int kk = 0; kk < 64; kk += 16) {
                uint32_t af[4];
                ldsm4(af[0], af[1], af[2], af[3],
                      pbu + (uint32_t)(((w * 16 + aRow) * LDA + koffA[t3] + kk + aCol) * 2));
                uint32_t bfr[4][2];
#pragma unroll
                for (int nt = 0; nt < 4; nt += 2) {
                    const int n0 = nt * 8;
                    ldsm4(bfr[nt][0], bfr[nt][1], bfr[nt + 1][0], bfr[nt + 1][1],
                          vbu + (uint32_t)(((n0 + bRow) * LDB + coffB[t3] + kk + bCol) * 2));
                }
#pragma unroll
                for (int nt = 0; nt < 4; nt++)
                    MMA16816(acc[nt], af, bfr[nt]);
            }
        }
        __syncwarp();
    }

#pragma unroll
    for (int nt = 0; nt < 4; nt++) {
        const int cg = nt * 8 + tig * 2;
#pragma unroll
        for (int half = 0; half < 2; half++) {
            const int rg = q0 + w * 16 + gid + half * 8;
            const float v0 = acc[nt][half * 2 + 0];
            const float v1 = acc[nt][half * 2 + 1];
            const long base = (long)rg * 512 + cg;
            *reinterpret_cast<__nv_bfloat162*>(&o3[base]) =
                __nv_bfloat162(__float2bfloat16(v0), __float2bfloat16(v1));
            *reinterpret_cast<__nv_bfloat162*>(&o3[base + 256]) =
                __nv_bfloat162(bf_lo(v0), bf_lo(v1));
        }
    }
}

// ---------------- fused weight split ----------------
struct WEnt { const float* src; __nv_bfloat16* dst; int R; int C; int tiles; };
struct WTab { WEnt e[13]; };

__global__ void wsplit_all(WTab tab)
{
    __shared__ float tile[128][33];
    int bid = blockIdx.x;
    int i = 0;
    while (bid >= tab.e[i].tiles) { bid -= tab.e[i].tiles; i++; }
    const float* in = tab.e[i].src;
    __nv_bfloat16* out = tab.e[i].dst;
    const int R = tab.e[i].R, C = tab.e[i].C;
    const int tC = C >> 5;
    const int r0 = (bid / tC) * 128, c0 = (bid % tC) * 32;

    for (int t = threadIdx.x; t < 128 * 32; t += 256) {
        int rr = t >> 5, cc = t & 31;
        tile[rr][cc] = in[(long)(r0 + rr) * C + c0 + cc];
    }
    __syncthreads();
    for (int t = threadIdx.x; t < 32 * 128; t += 256) {
        int cc = t >> 7, rr = t & 127;
        float v = tile[rr][cc];
        long ob = (long)(c0 + cc) * (2L * R) + (r0 + rr);
        out[ob] = __float2bfloat16(v);
        out[ob + R] = bf_lo(v);
    }
}

__global__ void pack_bias(const float* __restrict__ bq, const float* __restrict__ bk,
                          const float* __restrict__ bv, float* __restrict__ dst)
{
    const int l = blockIdx.x;
    const int d = threadIdx.x;
    float v;
    if (d < 256) v = bq[l * 256 + d];
    else if (d < 512) v = bk[l * 256 + d - 256];
    else v = bv[l * 256 + d - 512];
    dst[l * 768 + d] = v;
}

// ---------------- elementwise kernels ----------------

__global__ void embed_kernel(const int* __restrict__ node, const float* __restrict__ embed,
                             float* __restrict__ x, __nv_bfloat16* __restrict__ x3)
{
    const int row = blockIdx.x;
    const int d = threadIdx.x;
    const float v = embed[(long)node[row] * CD + d];
    x[(long)row * CD + d] = v;
    x3[(long)row * 512 + d] = __float2bfloat16(v);
    x3[(long)row * 512 + 256 + d] = bf_lo(v);
}

__global__ void tsplitB(const float* __restrict__ in, __nv_bfloat16* __restrict__ out,
                        int irs, int R, long sIn1, long sIn2, int divIn, long sOut)
{
    __shared__ float tile[128][33];
    const long z = blockIdx.z;
    in  += (z / divIn) * sIn1 + (z % divIn) * sIn2;
    out += z * sOut;
    const int r0 = blockIdx.x * 128, c0 = blockIdx.y * 32;
    for (int i = threadIdx.x; i < 128 * 32; i += 256) {
        int rr = i >> 5, cc = i & 31;
        tile[rr][cc] = in[(long)(r0 + rr) * irs + c0 + cc];
    }
    __syncthreads();
    for (int i = threadIdx.x; i < 32 * 128; i += 256) {
        int cc = i >> 7, rr = i & 127;
        float v = tile[rr][cc];
        long ob = (long)(c0 + cc) * (2L * R) + (r0 + rr);
        out[ob] = __float2bfloat16(v);
        out[ob + R] = bf_lo(v);
    }
}

// q3/k3 dedup'd to 64 phys wide per (b,h)
__global__ void qk_split(const float* __restrict__ qkv,
                         __nv_bfloat16* __restrict__ q3, __nv_bfloat16* __restrict__ k3)
{
    const int row = blockIdx.x;
    const int b = row >> 9, i = row & 511;
    const int d = threadIdx.x;
    const int h = d >> 5, dd = d & 31;
    const long base = ((long)(b * CH + h) * CN + i) * 64;
    float qv = qkv[(long)row * 768 + d];
    float kv = qkv[(long)row * 768 + 256 + d];
    q3[base + dd] = __float2bfloat16(qv);
    q3[base + 32 + dd] = bf_lo(qv);
    k3[base + dd] = __float2bfloat16(kv);
    k3[base + 32 + dd] = bf_lo(kv);
}

__global__ void e12_kernel(const float* __restrict__ h, const float* __restrict__ a1,
                           const float* __restrict__ a2, float* __restrict__ e1, float* __restrict__ e2)
{
    const int row = blockIdx.x;
    const int d = threadIdx.x;
    __shared__ float s1[256], s2[256];
    const float hv = h[(long)row * CD + d];
    s1[d] = hv * a1[d];
    s2[d] = hv * a2[d];
    __syncthreads();
    for (int off = 128; off > 0; off >>= 1) {
        if (d < off) { s1[d] += s1[d + off]; s2[d] += s2[d + off]; }
        __syncthreads();
    }
    if (d == 0) { e1[row] = s1[0]; e2[row] = s2[0]; }
}

__global__ void gat_softmax_kernel(const float* __restrict__ e1, const float* __restrict__ e2,
                                   const int* __restrict__ edge, __nv_bfloat16* __restrict__ al3)
{
    const int row = blockIdx.x;
    const int b = row / CN;
    const int t = threadIdx.x;
    __shared__ float red[256];
    const float ei = e1[row];
    float vals[2];
#pragma unroll
    for (int p = 0; p < 2; p++) {
        const int j = t + p * 256;
        float e = ei + e2[b * CN + j];
        e = (e >= 0.f) ? e : 0.2f * e;
        vals[p] = (edge[(long)row * CN + j] > 0) ? e : NEG_INF_F;
    }
    red[t] = fmaxf(vals[0], vals[1]);
    __syncthreads();
    for (int off = 128; off > 0; off >>= 1) { if (t < off) red[t] = fmaxf(red[t], red[t + off]); __syncthreads(); }
    const float m = red[0];
    __syncthreads();
    float ex[2] = {__expf(vals[0] - m), __expf(vals[1] - m)};
    red[t] = ex[0] + ex[1];
    __syncthreads();
    for (int off = 128; off > 0; off >>= 1) { if (t < off) red[t] += red[t + off]; __syncthreads(); }
    const float inv = 1.f / red[0];
    const long b3 = (long)row * 1024;
#pragma unroll
    for (int p = 0; p < 2; p++) {
        const int j = t + p * 256;
        const float pr = ex[p] * inv;
        al3[b3 + j] = __float2bfloat16(pr);
        al3[b3 + 512 + j] = bf_lo(pr);
    }
}

__global__ void scale_pe_kernel(float* __restrict__ x, __nv_bfloat16* __restrict__ x3)
{
    const int row = blockIdx.x;
    const int n = row % CN;
    const int d = threadIdx.x;
    const float expo = (2.0f * (float)(d >> 1)) / (float)CD;
    const float angle = (float)n * powf(10000.0f, -expo);
    const float pe = (d & 1) ? cosf(angle) : sinf(angle);
    const long idx = (long)row * CD + d;
    const float v = x[idx] * 16.0f + pe;
    x[idx] = v;
    x3[(long)row * 512 + d] = __float2bfloat16(v);
    x3[(long)row * 512 + 256 + d] = bf_lo(v);
}

__global__ void ln_kernel(const float* __restrict__ x, const float* __restrict__ delta,
                          const float* __restrict__ g, const float* __restrict__ bb,
                          float* __restrict__ out, __nv_bfloat16* __restrict__ x3)
{
    const int row = blockIdx.x;
    const int d = threadIdx.x;
    __shared__ float red[256];
    const long idx = (long)row * CD + d;
    const float v = x[idx] + delta[idx];
    red[d] = v;
    __syncthreads();
    for (int off = 128; off > 0; off >>= 1) { if (d < off) red[d] += red[d + off]; __syncthreads(); }
    const float mu = red[0] * (1.0f / CD);
    __syncthreads();
    const float c = v - mu;
    red[d] = c * c;
    __syncthreads();
    for (int off = 128; off > 0; off >>= 1) { if (d < off) red[d] += red[d + off]; __syncthreads(); }
    const float var = red[0] * (1.0f / CD);
    const float r = c * rsqrtf(var + 1e-6f) * g[d] + bb[d];
    out[idx] = r;
    if (x3) {
        x3[(long)row * 512 + d] = __float2bfloat16(r);
        x3[(long)row * 512 + 256 + d] = bf_lo(r);
    }
}

// ---------------- host ----------------
struct G3 { __nv_bfloat16* p; long s1; long s2; int ld; int seg; };

static void launch_gemm64(const __nv_bfloat16* A, const __nv_bfloat16* B, const float* bias, float* C,
                          int M, int N, int K3, int lda, int ldb, int ldc, int mapA, int mapB,
                          long sA, long sB, long sC1, long sC2, int divC,
                          float scale, int act, int batch, G3 g3)
{
    dim3 g(N / 64, M / 64, batch);
    size_t sm = 3 * (64 + 64) * 72 * 2;
    gemm_mma<64, 64, 64><<<g, 128, sm>>>(A, B, bias, C, lda, ldb, ldc, K3, mapA, mapB,
        sA, sB, sC1, sC2, divC, scale, act, g3.p, g3.s1, g3.s2, g3.ld, g3.seg);
}
static void launch_gemm32(const __nv_bfloat16* A, const __nv_bfloat16* B, float* C,
                          int M, int N, int K3, int lda, int ldb, int ldc, int mapA, int mapB,
                          long sA, long sB, long sC1, float scale, int batch)
{
    dim3 g(N / 64, M / 64, batch);
    size_t sm = 3 * (64 + 64) * 40 * 2;
    gemm_mma<64, 64, 32><<<g, 128, sm>>>(A, B, nullptr, C, lda, ldb, ldc, K3, mapA, mapB,
        sA, sB, sC1, 0, 1, scale, 0, nullptr, 0, 0, 0, 0);
}

extern "C" void kernel_launch(void* const* d_in, const int* in_sizes, int n_in,
                              void* d_out, int out_size)
{
    const int*   node  = (const int*)  d_in[0];
    const int*   edge  = (const int*)  d_in[1];
    const int*   mask  = (const int*)  d_in[2];
    const float* embed = (const float*)d_in[4];
    const float* Wg    = (const float*)d_in[5];
    const float* a1    = (const float*)d_in[6];
    const float* a2    = (const float*)d_in[7];
    const float* Wq    = (const float*)d_in[8];
    const float* bq    = (const float*)d_in[9];
    const float* Wk    = (const float*)d_in[10];
    const float* bk    = (const float*)d_in[11];
    const float* Wv    = (const float*)d_in[12];
    const float* bv    = (const float*)d_in[13];
    const float* Wo    = (const float*)d_in[14];
    const float* bo    = (const float*)d_in[15];
    const float* W1    = (const float*)d_in[16];
    const float* b1    = (const float*)d_in[17];
    const float* W2    = (const float*)d_in[18];
    const float* b2    = (const float*)d_in[19];
    const float* ln1g  = (const float*)d_in[20];
    const float* ln1b  = (const float*)d_in[21];
    const float* ln2g  = (const float*)d_in[22];
    const float* ln2b  = (const float*)d_in[23];

    cudaFuncSetAttribute((const void*)gemm_mma<64,64,64>, cudaFuncAttributeMaxDynamicSharedMemorySize, 60000);
    cudaFuncSetAttribute((const void*)gemm_mma<64,64,32>, cudaFuncAttributeMaxDynamicSharedMemorySize, 40000);
    cudaFuncSetAttribute((const void*)softmax_av, cudaFuncAttributeMaxDynamicSharedMemorySize, 90000);

    float *x, *h, *qkv, *t, *e1, *e2, *bias3;
    __nv_bfloat16 *x3, *o3, *ff3, *h3t, *al3, *q3, *k3, *v3t;
    __nv_bfloat16 *wg3, *wqkv3, *wo3, *w13, *w23;
    cudaGetSymbolAddress((void**)&x, g_x);     cudaGetSymbolAddress((void**)&h, g_h);
    cudaGetSymbolAddress((void**)&qkv, g_qkv); cudaGetSymbolAddress((void**)&t, g_t);
    cudaGetSymbolAddress((void**)&e1, g_e1);   cudaGetSymbolAddress((void**)&e2, g_e2);
    cudaGetSymbolAddress((void**)&bias3, g_bias);
    cudaGetSymbolAddress((void**)&x3, g_x3);   cudaGetSymbolAddress((void**)&o3, g_o3);
    cudaGetSymbolAddress((void**)&ff3, g_ff3); cudaGetSymbolAddress((void**)&h3t, g_h3t);
    cudaGetSymbolAddress((void**)&al3, g_al3);
    cudaGetSymbolAddress((void**)&q3, g_q3);   cudaGetSymbolAddress((void**)&k3, g_k3);
    cudaGetSymbolAddress((void**)&v3t, g_v3t);
    cudaGetSymbolAddress((void**)&wg3, g_wg3); cudaGetSymbolAddress((void**)&wqkv3, g_wqkv3);
    cudaGetSymbolAddress((void**)&wo3, g_wo3); cudaGetSymbolAddress((void**)&w13, g_w13);
    cudaGetSymbolAddress((void**)&w23, g_w23);

    float* out_x    = (float*)d_out;
    float* out_attn = (float*)d_out + (long)CB * CN * CD;

    const int M = CB * CN;
    const long ND = (long)CN * CD;
    const float inv_sqrt_dh = 0.17677669529663687f;
    const G3 no3 = {nullptr, 0, 0, 0, 0};

    WTab tab;
    int nTiles = 0;
    auto add = [&](int i, const float* src, __nv_bfloat16* dst, int R, int C) {
        tab.e[i] = {src, dst, R, C, (R / 128) * (C / 32)};
        nTiles += tab.e[i].tiles;
    };
    add(0, Wg, wg3, 256, 256);
    for (int l = 0; l < CL; l++) {
        const long w256 = (long)l * 65536, w1k = (long)l * 262144;
        add(1 + l * 6, Wq + w256, wqkv3 + (long)l * 768 * 512, 256, 256);
        add(2 + l * 6, Wk + w256, wqkv3 + (long)l * 768 * 512 + 256 * 512, 256, 256);
        add(3 + l * 6, Wv + w256, wqkv3 + (long)l * 768 * 512 + 512 * 512, 256, 256);
        add(4 + l * 6, Wo + w256, wo3 + (long)l * 256 * 512, 256, 256);
        add(5 + l * 6, W1 + w1k, w13 + (long)l * 1024 * 512, 256, 1024);
        add(6 + l * 6, W2 + w1k, w23 + (long)l * 256 * 2048, 1024, 256);
    }
    wsplit_all<<<nTiles, 256>>>(tab);
    pack_bias<<<CL, 768>>>(bq, bk, bv, bias3);

    embed_kernel<<<M, CD>>>(node, embed, x, x3);

    for (int hop = 0; hop < 2; hop++) {
        launch_gemm64(x3, wg3, nullptr, h, M, CD, 768, 512, 512, CD, 256, 256,
                      0, 0, 0, 0, 1, 1.f, 0, 1, no3);
        tsplitB<<<dim3(4, 8, CB), 256>>>(h, h3t, CD, CN, ND, 0, 1, (long)CD * 1024);
        e12_kernel<<<M, CD>>>(h, a1, a2, e1, e2);
        gat_softmax_kernel<<<M, 256>>>(e1, e2, edge, al3);
        // x fp32 only needed after hop 1 (scale_pe); hop 0 emits x3 only
        G3 gx3 = {x3, (long)CN * 512, 0, 512, 256};
        launch_gemm64(al3, h3t, nullptr, hop == 1 ? x : nullptr, CN, CD, 1536,
                      1024, 1024, CD, 512, 512,
                      (long)CN * 1024, (long)CD * 1024, ND, 0, 1, 1.f, 2, CB, gx3);
    }

    scale_pe_kernel<<<M, CD>>>(x, x3);

    for (int l = 0; l < CL; l++) {
        launch_gemm64(x3, wqkv3 + (long)l * 768 * 512, bias3 + l * 768, qkv,
                      M, 768, 768, 512, 512, 768, 256, 256,
                      0, 0, 0, 0, 1, 1.f, 0, 1, no3);

        qk_split<<<M, 256>>>(qkv, q3, k3);
        tsplitB<<<dim3(4, 1, CB * CH), 256>>>(qkv + 512, v3t, 768, CN,
                                              (long)CN * 768, 32, CH, 32L * 1024);

        // scores: K3=96 (dh=32 x 3 terms), BK=32, dedup'd q3/k3 (64 phys)
        launch_gemm32(q3, k3, out_attn, CN, CN, 96, 64, 64, CN, 32, 32,
                      (long)CN * 64, (long)CN * 64, (long)CN * CN,
                      inv_sqrt_dh, CB * CH);

        softmax_av<<<dim3(8, 1, CB * CH), 128, (32 * 1032 + 64 * 136) * 2>>>(
            out_attn, mask, v3t, o3, l == CL - 1 ? 1 : 0);

        launch_gemm64(o3, wo3 + (long)l * 256 * 512, bo + l * CD, t, M, CD, 768,
                      512, 512, CD, 256, 256,
                      0, 0, 0, 0, 1, 1.f, 0, 1, no3);
        ln_kernel<<<M, CD>>>(x, t, ln1g + l * CD, ln1b + l * CD, x, x3);

        // FFN1: fp32 output unused -> C=nullptr, only ff3 emitted
        G3 gff3 = {ff3, 0, 0, 2048, 1024};
        launch_gemm64(x3, w13 + (long)l * 1024 * 512, b1 + l * CDFF, nullptr,
                      M, CDFF, 768, 512, 512, CDFF, 256, 256,
                      0, 0, 0, 0, 1, 1.f, 1, 1, gff3);
        launch_gemm64(ff3, w23 + (long)l * 256 * 2048, b2 + l * CD, t, M, CD, 3072,
                      2048, 2048, CD, 1024, 1024,
                      0, 0, 0, 0, 1, 1.f, 0, 1, no3);
        const bool last = (l == CL - 1);
        ln_kernel<<<M, CD>>>(x, t, ln2g + l * CD, ln2b + l * CD,
                             last ? out_x : x, last ? nullptr : x3);
    }
}

// round 14
// speedup vs baseline: 1.0444x; 1.0245x over previous
#include <cuda_runtime.h>
#include <cuda_bf16.h>
#include <math.h>
#include <stdint.h>

#define CB 16
#define CN 512
#define CD 256
#define CH 8
#define CDFF 1024
#define CL 2
#define NEG_INF_F (-1e9f)

// ---------------- scratch (dedup'd split tensors) ----------------
static __device__ __align__(256) float g_x  [CB*CN*CD];
static __device__ __align__(256) float g_h  [CB*CN*CD];
static __device__ __align__(256) float g_qkv[CB*CN*768];
static __device__ __align__(256) float g_t  [CB*CN*CD];
static __device__ __align__(256) float g_e1 [CB*CN];
static __device__ __align__(256) float g_e2 [CB*CN];
static __device__ __align__(256) float g_bias[CL*768];
static __device__ __align__(256) float g_sc [64L*CN*CN];   // 67MB: half-batch scores (L2-resident)

static __device__ __align__(256) __nv_bfloat16 g_x3  [CB*CN*512];
static __device__ __align__(256) __nv_bfloat16 g_o3  [CB*CN*512];
static __device__ __align__(256) __nv_bfloat16 g_ff3 [CB*CN*2048];
static __device__ __align__(256) __nv_bfloat16 g_h3t [CB*CD*1024];
static __device__ __align__(256) __nv_bfloat16 g_al3 [CB*CN*1024];
static __device__ __align__(256) __nv_bfloat16 g_q3  [CB*CH*CN*64];
static __device__ __align__(256) __nv_bfloat16 g_k3  [CB*CH*CN*64];
static __device__ __align__(256) __nv_bfloat16 g_v3t [CB*CH*32*1024];
static __device__ __align__(256) __nv_bfloat16 g_wg3 [CD*512];
static __device__ __align__(256) __nv_bfloat16 g_wqkv3[CL*768*512];
static __device__ __align__(256) __nv_bfloat16 g_wo3 [CL*CD*512];
static __device__ __align__(256) __nv_bfloat16 g_w13 [CL*CDFF*512];
static __device__ __align__(256) __nv_bfloat16 g_w23 [CL*CD*2048];

__device__ __forceinline__ __nv_bfloat16 bf_lo(float v) {
    __nv_bfloat16 h = __float2bfloat16(v);
    return __float2bfloat16(v - __bfloat162float(h));
}
__device__ __forceinline__ void cpa16(uint32_t s, const void* g) {
    asm volatile("cp.async.cg.shared.global [%0], [%1], 16;" :: "r"(s), "l"(g));
}
__device__ __forceinline__ void ldsm4(uint32_t& r0, uint32_t& r1, uint32_t& r2, uint32_t& r3, uint32_t addr) {
    asm volatile("ldmatrix.sync.aligned.m8n8.x4.shared.b16 {%0,%1,%2,%3}, [%4];"
                 : "=r"(r0), "=r"(r1), "=r"(r2), "=r"(r3) : "r"(addr));
}
#define MMA16816(acc, a, b) \
    asm volatile("mma.sync.aligned.m16n8k16.row.col.f32.bf16.bf16.f32 " \
                 "{%0,%1,%2,%3}, {%4,%5,%6,%7}, {%8,%9}, {%0,%1,%2,%3};" \
                 : "+f"((acc)[0]), "+f"((acc)[1]), "+f"((acc)[2]), "+f"((acc)[3]) \
                 : "r"((a)[0]), "r"((a)[1]), "r"((a)[2]), "r"((a)[3]), \
                   "r"((b)[0]), "r"((b)[1]))

// ---------------- 3-stage cp.async mma.sync bf16 GEMM, chunk-remapped, C nullable ----------------
template<int BM, int TN, int BK>
__global__ __launch_bounds__((BM/32)*(TN/32)*32)
void gemm_mma(const __nv_bfloat16* __restrict__ A, const __nv_bfloat16* __restrict__ B,
              const float* __restrict__ bias, float* __restrict__ C,
              int lda, int ldb, int ldc, int K3, int mapA, int mapB,
              long strA, long strB, long sC1, long sC2, int divC,
              float scale, int act,
              __nv_bfloat16* __restrict__ C3, long sC31, long sC32, int ldc3, int seg3)
{
    constexpr int WM = 32, WN = 32;
    constexpr int LDS = BK + 8;
    constexpr int MT = 2, NT = 4;
    constexpr int WCOLS = TN / WN;
    constexpr int THREADS = (BM / WM) * (TN / WN) * 32;
    constexpr int AITERS = BM * (BK / 8) / THREADS;
    constexpr int BITERS = TN * (BK / 8) / THREADS;
    constexpr int STAGES = 3;

    extern __shared__ __nv_bfloat16 smem[];
    __nv_bfloat16* sA = smem;
    __nv_bfloat16* sB = smem + STAGES * BM * LDS;

    const long z = blockIdx.z;
    A += z * strA;
    B += z * strB;
    if (C)  C  += (z / divC) * sC1 + (z % divC) * sC2;
    if (C3) C3 += (z / divC) * sC31 + (z % divC) * sC32;
    const int row0 = blockIdx.y * BM;
    const int col0 = blockIdx.x * TN;

    const int tid = threadIdx.x;
    const int w = tid >> 5, lane = tid & 31;
    const int wr = w / WCOLS, wc = w % WCOLS;
    const int gid = lane >> 2, tig = lane & 3;

    uint32_t sAu = (uint32_t)__cvta_generic_to_shared(sA);
    uint32_t sBu = (uint32_t)__cvta_generic_to_shared(sB);

    const int aRow = lane & 15, aCol = (lane >> 4) << 3;
    const int bRow = ((lane >> 4) << 3) + (lane & 7), bCol = ((lane >> 3) & 1) << 3;

    float acc[MT][NT][4];
#pragma unroll
    for (int mt = 0; mt < MT; mt++)
#pragma unroll
        for (int nt = 0; nt < NT; nt++)
#pragma unroll
            for (int i = 0; i < 4; i++) acc[mt][nt][i] = 0.f;

    const int nChunks = K3 / BK;

    auto issue = [&](int s) {
        const int buf = s % STAGES;
        const int k0 = s * BK;
        const int k0a = mapA ? (k0 < 2 * mapA ? k0 : k0 - 2 * mapA) : k0;
        const int k0b = mapB ? (k0 < mapB ? k0 : k0 - mapB) : k0;
#pragma unroll
        for (int i = 0; i < AITERS; i++) {
            const int idx = i * THREADS + tid;
            const int r = idx / (BK / 8), kc = (idx % (BK / 8)) * 8;
            cpa16(sAu + (uint32_t)(((buf * BM + r) * LDS + kc) * 2),
                  A + (long)(row0 + r) * lda + k0a + kc);
        }
#pragma unroll
        for (int i = 0; i < BITERS; i++) {
            const int idx = i * THREADS + tid;
            const int r = idx / (BK / 8), kc = (idx % (BK / 8)) * 8;
            cpa16(sBu + (uint32_t)(((buf * TN + r) * LDS + kc) * 2),
                  B + (long)(col0 + r) * ldb + k0b + kc);
        }
        asm volatile("cp.async.commit_group;");
    };

    issue(0);
    if (nChunks > 1) issue(1);
    for (int c = 0; c < nChunks; c++) {
        if (c + 2 < nChunks) issue(c + 2);
        const int rem = nChunks - 1 - c;
        if (rem >= 2)      asm volatile("cp.async.wait_group 2;");
        else if (rem == 1) asm volatile("cp.async.wait_group 1;");
        else               asm volatile("cp.async.wait_group 0;");
        __syncthreads();

        const int buf = c % STAGES;
        const uint32_t aBase = sAu + (uint32_t)(buf * BM * LDS * 2);
        const uint32_t bBase = sBu + (uint32_t)(buf * TN * LDS * 2);
#pragma unroll
        for (int kk = 0; kk < BK; kk += 16) {
            uint32_t af[MT][4], bfr[NT][2];
#pragma unroll
            for (int mt = 0; mt < MT; mt++) {
                const int r = wr * WM + mt * 16;
                ldsm4(af[mt][0], af[mt][1], af[mt][2], af[mt][3],
                      aBase + (uint32_t)(((r + aRow) * LDS + kk + aCol) * 2));
            }
#pragma unroll
            for (int nt = 0; nt < NT; nt += 2) {
                const int n0 = wc * WN + nt * 8;
                ldsm4(bfr[nt][0], bfr[nt][1], bfr[nt + 1][0], bfr[nt + 1][1],
                      bBase + (uint32_t)(((n0 + bRow) * LDS + kk + bCol) * 2));
            }
#pragma unroll
            for (int mt = 0; mt < MT; mt++)
#pragma unroll
                for (int nt = 0; nt < NT; nt++)
                    MMA16816(acc[mt][nt], af[mt], bfr[nt]);
        }
        __syncthreads();
    }

    // epilogue
#pragma unroll
    for (int mt = 0; mt < MT; mt++) {
#pragma unroll
        for (int nt = 0; nt < NT; nt++) {
            const int rloc = wr * WM + mt * 16 + gid;
            const int cloc = wc * WN + nt * 8 + tig * 2;
            const int cg = col0 + cloc;
            float b0 = bias ? bias[cg] : 0.f;
            float b1 = bias ? bias[cg + 1] : 0.f;
#pragma unroll
            for (int half = 0; half < 2; half++) {
                const int rg = row0 + rloc + half * 8;
                float v0 = acc[mt][nt][half * 2 + 0] * scale + b0;
                float v1 = acc[mt][nt][half * 2 + 1] * scale + b1;
                if (act == 1) { v0 = fmaxf(v0, 0.f); v1 = fmaxf(v1, 0.f); }
                else if (act == 2) {
                    v0 = (v0 > 0.f) ? v0 : expm1f(v0);
                    v1 = (v1 > 0.f) ? v1 : expm1f(v1);
                }
                if (C)
                    *reinterpret_cast<float2*>(&C[(long)rg * ldc + cg]) = make_float2(v0, v1);
                if (C3) {
                    long base = (long)rg * ldc3 + cg;
                    *reinterpret_cast<__nv_bfloat162*>(&C3[base]) =
                        __nv_bfloat162(__float2bfloat16(v0), __float2bfloat16(v1));
                    *reinterpret_cast<__nv_bfloat162*>(&C3[base + seg3]) =
                        __nv_bfloat162(bf_lo(v0), bf_lo(v1));
                }
            }
        }
    }
}

// ---------------- fused softmax + attn@v (half-batch, scores from L2 scratch) ----------------
__global__ __launch_bounds__(128)
void softmax_av(const float* __restrict__ s, const int* __restrict__ mask,
                const __nv_bfloat16* __restrict__ v3t,
                __nv_bfloat16* __restrict__ o3,
                float* __restrict__ probsOut, int headBase)
{
    constexpr int LDA = 136;
    constexpr int LDB = 1032;
    extern __shared__ __nv_bfloat16 dsm[];
    __nv_bfloat16* vbuf = dsm;
    __nv_bfloat16* pbuf = dsm + 32 * LDB;
    __shared__ float rowm[64], rowinv[64];

    const int zz = blockIdx.z;              // 0..63 local
    const int g = headBase + zz;            // global head id = b*CH + h
    const int q0 = blockIdx.x * 64;
    const int mb = (g >> 3) * CN;
    const float* sbase = s + (long)zz * CN * CN;
    float* pout = probsOut ? probsOut + (long)zz * CN * CN : nullptr;
    const __nv_bfloat16* vb = v3t + (long)g * 32 * 1024;
    o3 += (long)(g >> 3) * ((long)CN * 512) + (g & 7) * 32;

    const int tid = threadIdx.x;
    const int w = tid >> 5, lane = tid & 31;
    const int gid = lane >> 2, tig = lane & 3;

    uint32_t vbu = (uint32_t)__cvta_generic_to_shared(vbuf);
    uint32_t pbu = (uint32_t)__cvta_generic_to_shared(pbuf);

#pragma unroll
    for (int i = 0; i < 32; i++) {
        const int idx = i * 128 + tid;
        const int r = idx >> 7, ch = idx & 127;
        cpa16(vbu + (uint32_t)((r * LDB + ch * 8) * 2), vb + r * 1024 + ch * 8);
    }
    asm volatile("cp.async.commit_group;");

    for (int i = 0; i < 16; i++) {
        const int r = w * 16 + i;
        const float* srow = sbase + (long)(q0 + r) * CN;
        float mx = -1e30f;
        for (int j = lane; j < CN; j += 32)
            mx = fmaxf(mx, srow[j] + (float)mask[mb + j] * NEG_INF_F);
#pragma unroll
        for (int off = 16; off > 0; off >>= 1)
            mx = fmaxf(mx, __shfl_xor_sync(0xffffffffu, mx, off));
        float sum = 0.f;
        for (int j = lane; j < CN; j += 32)
            sum += __expf(srow[j] + (float)mask[mb + j] * NEG_INF_F - mx);
#pragma unroll
        for (int off = 16; off > 0; off >>= 1)
            sum += __shfl_xor_sync(0xffffffffu, sum, off);
        if (lane == 0) { rowm[r] = mx; rowinv[r] = 1.f / sum; }
    }
    asm volatile("cp.async.wait_group 0;");
    __syncthreads();

    const int aRow = lane & 15, aCol = (lane >> 4) << 3;
    const int bRow = ((lane >> 4) << 3) + (lane & 7), bCol = ((lane >> 3) & 1) << 3;

    float acc[4][4];
#pragma unroll
    for (int nt = 0; nt < 4; nt++)
#pragma unroll
        for (int i = 0; i < 4; i++) acc[nt][i] = 0.f;

    for (int jc = 0; jc < 8; jc++) {
#pragma unroll
        for (int i = 0; i < 16; i++) {
            const int r = w * 16 + i;
            const int j = jc * 64 + lane * 2;
            const float* sp = sbase + (long)(q0 + r) * CN + j;
            float2 v2 = *reinterpret_cast<const float2*>(sp);
            const float m = rowm[r], inv = rowinv[r];
            float p0 = __expf(v2.x + (float)mask[mb + j] * NEG_INF_F - m) * inv;
            float p1 = __expf(v2.y + (float)mask[mb + j + 1] * NEG_INF_F - m) * inv;
            if (pout)
                *reinterpret_cast<float2*>(&pout[(long)(q0 + r) * CN + j]) = make_float2(p0, p1);
            *reinterpret_cast<__nv_bfloat162*>(&pbuf[r * LDA + lane * 2]) =
                __nv_bfloat162(__float2bfloat16(p0), __float2bfloat16(p1));
            *reinterpret_cast<__nv_bfloat162*>(&pbuf[r * LDA + 64 + lane * 2]) =
                __nv_bfloat162(bf_lo(p0), bf_lo(p1));
        }
        __syncwarp();
        const int koffA[3] = {0, 64, 0};
        const int coffB[3] = {jc * 64, jc * 64, 512 + jc * 64};
#pragma unroll
        for (int t3 = 0; t3 < 3; t3++) {
#pragma unroll
            for (int kk = 0; kk < 64; kk += 16) {
                uint32_t af[4];
                ldsm4(af[0], af[1], af[2], af[3],
                      pbu + (uint32_t)(((w * 16 + aRow) * LDA + koffA[t3] + kk + aCol) * 2));
                uint32_t bfr[4][2];
#pragma unroll
                for (int nt = 0; nt < 4; nt += 2) {
                    const int n0 = nt * 8;
                    ldsm4(bfr[nt][0], bfr[nt][1], bfr[nt + 1][0], bfr[nt + 1][1],
                          vbu + (uint32_t)(((n0 + bRow) * LDB + coffB[t3] + kk + bCol) * 2));
                }
#pragma unroll
                for (int nt = 0; nt < 4; nt++)
                    MMA16816(acc[nt], af, bfr[nt]);
            }
        }
        __syncwarp();
    }

#pragma unroll
    for (int nt = 0; nt < 4; nt++) {
        const int cg = nt * 8 + tig * 2;
#pragma unroll
        for (int half = 0; half < 2; half++) {
            const int rg = q0 + w * 16 + gid + half * 8;
            const float v0 = acc[nt][half * 2 + 0];
            const float v1 = acc[nt][half * 2 + 1];
            const long base = (long)rg * 512 + cg;
            *reinterpret_cast<__nv_bfloat162*>(&o3[base]) =
                __nv_bfloat162(__float2bfloat16(v0), __float2bfloat16(v1));
            *reinterpret_cast<__nv_bfloat162*>(&o3[base + 256]) =
                __nv_bfloat162(bf_lo(v0), bf_lo(v1));
        }
    }
}

// ---------------- fused weight split ----------------
struct WEnt { const float* src; __nv_bfloat16* dst; int R; int C; int tiles; };
struct WTab { WEnt e[13]; };

__global__ void wsplit_all(WTab tab)
{
    __shared__ float tile[128][33];
    int bid = blockIdx.x;
    int i = 0;
    while (bid >= tab.e[i].tiles) { bid -= tab.e[i].tiles; i++; }
    const float* in = tab.e[i].src;
    __nv_bfloat16* out = tab.e[i].dst;
    const int R = tab.e[i].R, C = tab.e[i].C;
    const int tC = C >> 5;
    const int r0 = (bid / tC) * 128, c0 = (bid % tC) * 32;

    for (int t = threadIdx.x; t < 128 * 32; t += 256) {
        int rr = t >> 5, cc = t & 31;
        tile[rr][cc] = in[(long)(r0 + rr) * C + c0 + cc];
    }
    __syncthreads();
    for (int t = threadIdx.x; t < 32 * 128; t += 256) {
        int cc = t >> 7, rr = t & 127;
        float v = tile[rr][cc];
        long ob = (long)(c0 + cc) * (2L * R) + (r0 + rr);
        out[ob] = __float2bfloat16(v);
        out[ob + R] = bf_lo(v);
    }
}

__global__ void pack_bias(const float* __restrict__ bq, const float* __restrict__ bk,
                          const float* __restrict__ bv, float* __restrict__ dst)
{
    const int l = blockIdx.x;
    const int d = threadIdx.x;
    float v;
    if (d < 256) v = bq[l * 256 + d];
    else if (d < 512) v = bk[l * 256 + d - 256];
    else v = bv[l * 256 + d - 512];
    dst[l * 768 + d] = v;
}

// ---------------- elementwise kernels ----------------

__global__ void embed_kernel(const int* __restrict__ node, const float* __restrict__ embed,
                             float* __restrict__ x, __nv_bfloat16* __restrict__ x3)
{
    const int row = blockIdx.x;
    const int d = threadIdx.x;
    const float v = embed[(long)node[row] * CD + d];
    x[(long)row * CD + d] = v;
    x3[(long)row * 512 + d] = __float2bfloat16(v);
    x3[(long)row * 512 + 256 + d] = bf_lo(v);
}

__global__ void tsplitB(const float* __restrict__ in, __nv_bfloat16* __restrict__ out,
                        int irs, int R, long sIn1, long sIn2, int divIn, long sOut)
{
    __shared__ float tile[128][33];
    const long z = blockIdx.z;
    in  += (z / divIn) * sIn1 + (z % divIn) * sIn2;
    out += z * sOut;
    const int r0 = blockIdx.x * 128, c0 = blockIdx.y * 32;
    for (int i = threadIdx.x; i < 128 * 32; i += 256) {
        int rr = i >> 5, cc = i & 31;
        tile[rr][cc] = in[(long)(r0 + rr) * irs + c0 + cc];
    }
    __syncthreads();
    for (int i = threadIdx.x; i < 32 * 128; i += 256) {
        int cc = i >> 7, rr = i & 127;
        float v = tile[rr][cc];
        long ob = (long)(c0 + cc) * (2L * R) + (r0 + rr);
        out[ob] = __float2bfloat16(v);
        out[ob + R] = bf_lo(v);
    }
}

__global__ void qk_split(const float* __restrict__ qkv,
                         __nv_bfloat16* __restrict__ q3, __nv_bfloat16* __restrict__ k3)
{
    const int row = blockIdx.x;
    const int b = row >> 9, i = row & 511;
    const int d = threadIdx.x;
    const int h = d >> 5, dd = d & 31;
    const long base = ((long)(b * CH + h) * CN + i) * 64;
    float qv = qkv[(long)row * 768 + d];
    float kv = qkv[(long)row * 768 + 256 + d];
    q3[base + dd] = __float2bfloat16(qv);
    q3[base + 32 + dd] = bf_lo(qv);
    k3[base + dd] = __float2bfloat16(kv);
    k3[base + 32 + dd] = bf_lo(kv);
}

__global__ void e12_kernel(const float* __restrict__ h, const float* __restrict__ a1,
                           const float* __restrict__ a2, float* __restrict__ e1, float* __restrict__ e2)
{
    const int row = blockIdx.x;
    const int d = threadIdx.x;
    __shared__ float s1[256], s2[256];
    const float hv = h[(long)row * CD + d];
    s1[d] = hv * a1[d];
    s2[d] = hv * a2[d];
    __syncthreads();
    for (int off = 128; off > 0; off >>= 1) {
        if (d < off) { s1[d] += s1[d + off]; s2[d] += s2[d + off]; }
        __syncthreads();
    }
    if (d == 0) { e1[row] = s1[0]; e2[row] = s2[0]; }
}

__global__ void gat_softmax_kernel(const float* __restrict__ e1, const float* __restrict__ e2,
                                   const int* __restrict__ edge, __nv_bfloat16* __restrict__ al3)
{
    const int row = blockIdx.x;
    const int b = row / CN;
    const int t = threadIdx.x;
    __shared__ float red[256];
    const float ei = e1[row];
    float vals[2];
#pragma unroll
    for (int p = 0; p < 2; p++) {
        const int j = t + p * 256;
        float e = ei + e2[b * CN + j];
        e = (e >= 0.f) ? e : 0.2f * e;
        vals[p] = (edge[(long)row * CN + j] > 0) ? e : NEG_INF_F;
    }
    red[t] = fmaxf(vals[0], vals[1]);
    __syncthreads();
    for (int off = 128; off > 0; off >>= 1) { if (t < off) red[t] = fmaxf(red[t], red[t + off]); __syncthreads(); }
    const float m = red[0];
    __syncthreads();
    float ex[2] = {__expf(vals[0] - m), __expf(vals[1] - m)};
    red[t] = ex[0] + ex[1];
    __syncthreads();
    for (int off = 128; off > 0; off >>= 1) { if (t < off) red[t] += red[t + off]; __syncthreads(); }
    const float inv = 1.f / red[0];
    const long b3 = (long)row * 1024;
#pragma unroll
    for (int p = 0; p < 2; p++) {
        const int j = t + p * 256;
        const float pr = ex[p] * inv;
        al3[b3 + j] = __float2bfloat16(pr);
        al3[b3 + 512 + j] = bf_lo(pr);
    }
}

__global__ void scale_pe_kernel(float* __restrict__ x, __nv_bfloat16* __restrict__ x3)
{
    const int row = blockIdx.x;
    const int n = row % CN;
    const int d = threadIdx.x;
    const float expo = (2.0f * (float)(d >> 1)) / (float)CD;
    const float angle = (float)n * powf(10000.0f, -expo);
    const float pe = (d & 1) ? cosf(angle) : sinf(angle);
    const long idx = (long)row * CD + d;
    const float v = x[idx] * 16.0f + pe;
    x[idx] = v;
    x3[(long)row * 512 + d] = __float2bfloat16(v);
    x3[(long)row * 512 + 256 + d] = bf_lo(v);
}

__global__ void ln_kernel(const float* __restrict__ x, const float* __restrict__ delta,
                          const float* __restrict__ g, const float* __restrict__ bb,
                          float* __restrict__ out, __nv_bfloat16* __restrict__ x3)
{
    const int row = blockIdx.x;
    const int d = threadIdx.x;
    __shared__ float red[256];
    const long idx = (long)row * CD + d;
    const float v = x[idx] + delta[idx];
    red[d] = v;
    __syncthreads();
    for (int off = 128; off > 0; off >>= 1) { if (d < off) red[d] += red[d + off]; __syncthreads(); }
    const float mu = red[0] * (1.0f / CD);
    __syncthreads();
    const float c = v - mu;
    red[d] = c * c;
    __syncthreads();
    for (int off = 128; off > 0; off >>= 1) { if (d < off) red[d] += red[d + off]; __syncthreads(); }
    const float var = red[0] * (1.0f / CD);
    const float r = c * rsqrtf(var + 1e-6f) * g[d] + bb[d];
    out[idx] = r;
    if (x3) {
        x3[(long)row * 512 + d] = __float2bfloat16(r);
        x3[(long)row * 512 + 256 + d] = bf_lo(r);
    }
}

// ---------------- host ----------------
struct G3 { __nv_bfloat16* p; long s1; long s2; int ld; int seg; };

static void launch_gemm64(const __nv_bfloat16* A, const __nv_bfloat16* B, const float* bias, float* C,
                          int M, int N, int K3, int lda, int ldb, int ldc, int mapA, int mapB,
                          long sA, long sB, long sC1, long sC2, int divC,
                          float scale, int act, int batch, G3 g3)
{
    dim3 g(N / 64, M / 64, batch);
    size_t sm = 3 * (64 + 64) * 72 * 2;
    gemm_mma<64, 64, 64><<<g, 128, sm>>>(A, B, bias, C, lda, ldb, ldc, K3, mapA, mapB,
        sA, sB, sC1, sC2, divC, scale, act, g3.p, g3.s1, g3.s2, g3.ld, g3.seg);
}
static void launch_gemm32(const __nv_bfloat16* A, const __nv_bfloat16* B, float* C,
                          int M, int N, int K3, int lda, int ldb, int ldc, int mapA, int mapB,
                          long sA, long sB, long sC1, float scale, int batch)
{
    dim3 g(N / 64, M / 64, batch);
    size_t sm = 3 * (64 + 64) * 40 * 2;
    gemm_mma<64, 64, 32><<<g, 128, sm>>>(A, B, nullptr, C, lda, ldb, ldc, K3, mapA, mapB,
        sA, sB, sC1, 0, 1, scale, 0, nullptr, 0, 0, 0, 0);
}

extern "C" void kernel_launch(void* const* d_in, const int* in_sizes, int n_in,
                              void* d_out, int out_size)
{
    const int*   node  = (const int*)  d_in[0];
    const int*   edge  = (const int*)  d_in[1];
    const int*   mask  = (const int*)  d_in[2];
    const float* embed = (const float*)d_in[4];
    const float* Wg    = (const float*)d_in[5];
    const float* a1    = (const float*)d_in[6];
    const float* a2    = (const float*)d_in[7];
    const float* Wq    = (const float*)d_in[8];
    const float* bq    = (const float*)d_in[9];
    const float* Wk    = (const float*)d_in[10];
    const float* bk    = (const float*)d_in[11];
    const float* Wv    = (const float*)d_in[12];
    const float* bv    = (const float*)d_in[13];
    const float* Wo    = (const float*)d_in[14];
    const float* bo    = (const float*)d_in[15];
    const float* W1    = (const float*)d_in[16];
    const float* b1    = (const float*)d_in[17];
    const float* W2    = (const float*)d_in[18];
    const float* b2    = (const float*)d_in[19];
    const float* ln1g  = (const float*)d_in[20];
    const float* ln1b  = (const float*)d_in[21];
    const float* ln2g  = (const float*)d_in[22];
    const float* ln2b  = (const float*)d_in[23];

    cudaFuncSetAttribute((const void*)gemm_mma<64,64,64>, cudaFuncAttributeMaxDynamicSharedMemorySize, 60000);
    cudaFuncSetAttribute((const void*)gemm_mma<64,64,32>, cudaFuncAttributeMaxDynamicSharedMemorySize, 40000);
    cudaFuncSetAttribute((const void*)softmax_av, cudaFuncAttributeMaxDynamicSharedMemorySize, 90000);

    float *x, *h, *qkv, *t, *e1, *e2, *bias3, *sc;
    __nv_bfloat16 *x3, *o3, *ff3, *h3t, *al3, *q3, *k3, *v3t;
    __nv_bfloat16 *wg3, *wqkv3, *wo3, *w13, *w23;
    cudaGetSymbolAddress((void**)&x, g_x);     cudaGetSymbolAddress((void**)&h, g_h);
    cudaGetSymbolAddress((void**)&qkv, g_qkv); cudaGetSymbolAddress((void**)&t, g_t);
    cudaGetSymbolAddress((void**)&e1, g_e1);   cudaGetSymbolAddress((void**)&e2, g_e2);
    cudaGetSymbolAddress((void**)&bias3, g_bias);
    cudaGetSymbolAddress((void**)&sc, g_sc);
    cudaGetSymbolAddress((void**)&x3, g_x3);   cudaGetSymbolAddress((void**)&o3, g_o3);
    cudaGetSymbolAddress((void**)&ff3, g_ff3); cudaGetSymbolAddress((void**)&h3t, g_h3t);
    cudaGetSymbolAddress((void**)&al3, g_al3);
    cudaGetSymbolAddress((void**)&q3, g_q3);   cudaGetSymbolAddress((void**)&k3, g_k3);
    cudaGetSymbolAddress((void**)&v3t, g_v3t);
    cudaGetSymbolAddress((void**)&wg3, g_wg3); cudaGetSymbolAddress((void**)&wqkv3, g_wqkv3);
    cudaGetSymbolAddress((void**)&wo3, g_wo3); cudaGetSymbolAddress((void**)&w13, g_w13);
    cudaGetSymbolAddress((void**)&w23, g_w23);

    float* out_x    = (float*)d_out;
    float* out_attn = (float*)d_out + (long)CB * CN * CD;

    const int M = CB * CN;
    const long ND = (long)CN * CD;
    const float inv_sqrt_dh = 0.17677669529663687f;
    const G3 no3 = {nullptr, 0, 0, 0, 0};

    WTab tab;
    int nTiles = 0;
    auto add = [&](int i, const float* src, __nv_bfloat16* dst, int R, int C) {
        tab.e[i] = {src, dst, R, C, (R / 128) * (C / 32)};
        nTiles += tab.e[i].tiles;
    };
    add(0, Wg, wg3, 256, 256);
    for (int l = 0; l < CL; l++) {
        const long w256 = (long)l * 65536, w1k = (long)l * 262144;
        add(1 + l * 6, Wq + w256, wqkv3 + (long)l * 768 * 512, 256, 256);
        add(2 + l * 6, Wk + w256, wqkv3 + (long)l * 768 * 512 + 256 * 512, 256, 256);
        add(3 + l * 6, Wv + w256, wqkv3 + (long)l * 768 * 512 + 512 * 512, 256, 256);
        add(4 + l * 6, Wo + w256, wo3 + (long)l * 256 * 512, 256, 256);
        add(5 + l * 6, W1 + w1k, w13 + (long)l * 1024 * 512, 256, 1024);
        add(6 + l * 6, W2 + w1k, w23 + (long)l * 256 * 2048, 1024, 256);
    }
    wsplit_all<<<nTiles, 256>>>(tab);
    pack_bias<<<CL, 768>>>(bq, bk, bv, bias3);

    embed_kernel<<<M, CD>>>(node, embed, x, x3);

    for (int hop = 0; hop < 2; hop++) {
        launch_gemm64(x3, wg3, nullptr, h, M, CD, 768, 512, 512, CD, 256, 256,
                      0, 0, 0, 0, 1, 1.f, 0, 1, no3);
        tsplitB<<<dim3(4, 8, CB), 256>>>(h, h3t, CD, CN, ND, 0, 1, (long)CD * 1024);
        e12_kernel<<<M, CD>>>(h, a1, a2, e1, e2);
        gat_softmax_kernel<<<M, 256>>>(e1, e2, edge, al3);
        G3 gx3 = {x3, (long)CN * 512, 0, 512, 256};
        launch_gemm64(al3, h3t, nullptr, hop == 1 ? x : nullptr, CN, CD, 1536,
                      1024, 1024, CD, 512, 512,
                      (long)CN * 1024, (long)CD * 1024, ND, 0, 1, 1.f, 2, CB, gx3);
    }

    scale_pe_kernel<<<M, CD>>>(x, x3);

    for (int l = 0; l < CL; l++) {
        launch_gemm64(x3, wqkv3 + (long)l * 768 * 512, bias3 + l * 768, qkv,
                      M, 768, 768, 512, 512, 768, 256, 256,
                      0, 0, 0, 0, 1, 1.f, 0, 1, no3);

        qk_split<<<M, 256>>>(qkv, q3, k3);
        tsplitB<<<dim3(4, 1, CB * CH), 256>>>(qkv + 512, v3t, 768, CN,
                                              (long)CN * 768, 32, CH, 32L * 1024);

        const bool last = (l == CL - 1);
        // attention in two 64-head halves; scores stay in 67MB L2-resident scratch
        for (int half = 0; half < 2; half++) {
            const long qkOff = (long)half * 64 * CN * 64;
            launch_gemm32(q3 + qkOff, k3 + qkOff, sc, CN, CN, 96, 64, 64, CN, 32, 32,
                          (long)CN * 64, (long)CN * 64, (long)CN * CN,
                          inv_sqrt_dh, 64);
            softmax_av<<<dim3(8, 1, 64), 128, (32 * 1032 + 64 * 136) * 2>>>(
                sc, mask, v3t, o3,
                last ? out_attn + (long)half * 64 * CN * CN : nullptr,
                half * 64);
        }

        launch_gemm64(o3, wo3 + (long)l * 256 * 512, bo + l * CD, t, M, CD, 768,
                      512, 512, CD, 256, 256,
                      0, 0, 0, 0, 1, 1.f, 0, 1, no3);
        ln_kernel<<<M, CD>>>(x, t, ln1g + l * CD, ln1b + l * CD, x, x3);

        G3 gff3 = {ff3, 0, 0, 2048, 1024};
        launch_gemm64(x3, w13 + (long)l * 1024 * 512, b1 + l * CDFF, nullptr,
                      M, CDFF, 768, 512, 512, CDFF, 256, 256,
                      0, 0, 0, 0, 1, 1.f, 1, 1, gff3);
        launch_gemm64(ff3, w23 + (long)l * 256 * 2048, b2 + l * CD, t, M, CD, 3072,
                      2048, 2048, CD, 1024, 1024,
                      0, 0, 0, 0, 1, 1.f, 0, 1, no3);
        ln_kernel<<<M, CD>>>(x, t, ln2g + l * CD, ln2b + l * CD,
                             last ? out_x : x, last ? nullptr : x3);
    }
}

// round 15
// speedup vs baseline: 1.3725x; 1.3142x over previous
#include <cuda_runtime.h>
#include <cuda_fp16.h>
#include <math.h>
#include <stdint.h>

#define CB 16
#define CN 512
#define CD 256
#define CH 8
#define CDFF 1024
#define CL 2
#define NEG_INF_F (-1e9f)

// ---------------- scratch ----------------
static __device__ __align__(256) float g_x  [CB*CN*CD];
static __device__ __align__(256) float g_h  [CB*CN*CD];
static __device__ __align__(256) float g_qkv[CB*CN*768];
static __device__ __align__(256) float g_t  [CB*CN*CD];
static __device__ __align__(256) float g_e1 [CB*CN];
static __device__ __align__(256) float g_e2 [CB*CN];
static __device__ __align__(256) float g_bias[CL*768];
static __device__ __align__(256) float g_sc [64L*CN*CN];   // 67MB half-batch scores (L2-resident)

static __device__ __align__(256) __half g_x3  [CB*CN*512];      // A [hi|lo]
static __device__ __align__(256) __half g_o3  [CB*CN*512];
static __device__ __align__(256) __half g_ff3 [CB*CN*2048];
static __device__ __align__(256) __half g_h3t [CB*CD*512];      // B hi-only
static __device__ __align__(256) __half g_al3 [CB*CN*1024];     // A [hi|lo]
static __device__ __align__(256) __half g_q3  [CB*CH*CN*64];    // A [hi|lo] per head
static __device__ __align__(256) __half g_k3  [CB*CH*CN*32];    // B hi-only per head
static __device__ __align__(256) __half g_v3t [CB*CH*32*512];   // B hi-only
static __device__ __align__(256) __half g_wg2 [CD*256];
static __device__ __align__(256) __half g_wqkv2[CL*768*256];
static __device__ __align__(256) __half g_wo2 [CL*CD*256];
static __device__ __align__(256) __half g_w12 [CL*CDFF*256];
static __device__ __align__(256) __half g_w22 [CL*CD*1024];

__device__ __forceinline__ __half f16lo(float v) {
    __half h = __float2half_rn(v);
    return __float2half_rn(v - __half2float(h));
}
__device__ __forceinline__ void cpa16(uint32_t s, const void* g) {
    asm volatile("cp.async.cg.shared.global [%0], [%1], 16;" :: "r"(s), "l"(g));
}
__device__ __forceinline__ void ldsm4(uint32_t& r0, uint32_t& r1, uint32_t& r2, uint32_t& r3, uint32_t addr) {
    asm volatile("ldmatrix.sync.aligned.m8n8.x4.shared.b16 {%0,%1,%2,%3}, [%4];"
                 : "=r"(r0), "=r"(r1), "=r"(r2), "=r"(r3) : "r"(addr));
}
#define MMA16816(acc, a, b) \
    asm volatile("mma.sync.aligned.m16n8k16.row.col.f32.f16.f16.f32 " \
                 "{%0,%1,%2,%3}, {%4,%5,%6,%7}, {%8,%9}, {%0,%1,%2,%3};" \
                 : "+f"((acc)[0]), "+f"((acc)[1]), "+f"((acc)[2]), "+f"((acc)[3]) \
                 : "r"((a)[0]), "r"((a)[1]), "r"((a)[2]), "r"((a)[3]), \
                   "r"((b)[0]), "r"((b)[1]))

// ---------------- 3-stage cp.async mma.sync fp16 GEMM, chunk-remapped, C nullable ----------------
template<int BM, int TN, int BK>
__global__ __launch_bounds__((BM/32)*(TN/32)*32)
void gemm_mma(const __half* __restrict__ A, const __half* __restrict__ B,
              const float* __restrict__ bias, float* __restrict__ C,
              int lda, int ldb, int ldc, int K3, int mapA, int mapB,
              long strA, long strB, long sC1, long sC2, int divC,
              float scale, int act,
              __half* __restrict__ C3, long sC31, long sC32, int ldc3, int seg3)
{
    constexpr int WM = 32, WN = 32;
    constexpr int LDS = BK + 8;
    constexpr int MT = 2, NT = 4;
    constexpr int WCOLS = TN / WN;
    constexpr int THREADS = (BM / WM) * (TN / WN) * 32;
    constexpr int AITERS = BM * (BK / 8) / THREADS;
    constexpr int BITERS = TN * (BK / 8) / THREADS;
    constexpr int STAGES = 3;

    extern __shared__ __half smem[];
    __half* sA = smem;
    __half* sB = smem + STAGES * BM * LDS;

    const long z = blockIdx.z;
    A += z * strA;
    B += z * strB;
    if (C)  C  += (z / divC) * sC1 + (z % divC) * sC2;
    if (C3) C3 += (z / divC) * sC31 + (z % divC) * sC32;
    const int row0 = blockIdx.y * BM;
    const int col0 = blockIdx.x * TN;

    const int tid = threadIdx.x;
    const int w = tid >> 5, lane = tid & 31;
    const int wr = w / WCOLS, wc = w % WCOLS;
    const int gid = lane >> 2, tig = lane & 3;

    uint32_t sAu = (uint32_t)__cvta_generic_to_shared(sA);
    uint32_t sBu = (uint32_t)__cvta_generic_to_shared(sB);

    const int aRow = lane & 15, aCol = (lane >> 4) << 3;
    const int bRow = ((lane >> 4) << 3) + (lane & 7), bCol = ((lane >> 3) & 1) << 3;

    float acc[MT][NT][4];
#pragma unroll
    for (int mt = 0; mt < MT; mt++)
#pragma unroll
        for (int nt = 0; nt < NT; nt++)
#pragma unroll
            for (int i = 0; i < 4; i++) acc[mt][nt][i] = 0.f;

    const int nChunks = K3 / BK;

    auto issue = [&](int s) {
        const int buf = s % STAGES;
        const int k0 = s * BK;
        const int k0a = mapA ? (k0 < 2 * mapA ? k0 : k0 - 2 * mapA) : k0;
        const int k0b = mapB ? (k0 < mapB ? k0 : k0 - mapB) : k0;
#pragma unroll
        for (int i = 0; i < AITERS; i++) {
            const int idx = i * THREADS + tid;
            const int r = idx / (BK / 8), kc = (idx % (BK / 8)) * 8;
            cpa16(sAu + (uint32_t)(((buf * BM + r) * LDS + kc) * 2),
                  A + (long)(row0 + r) * lda + k0a + kc);
        }
#pragma unroll
        for (int i = 0; i < BITERS; i++) {
            const int idx = i * THREADS + tid;
            const int r = idx / (BK / 8), kc = (idx % (BK / 8)) * 8;
            cpa16(sBu + (uint32_t)(((buf * TN + r) * LDS + kc) * 2),
                  B + (long)(col0 + r) * ldb + k0b + kc);
        }
        asm volatile("cp.async.commit_group;");
    };

    issue(0);
    if (nChunks > 1) issue(1);
    for (int c = 0; c < nChunks; c++) {
        if (c + 2 < nChunks) issue(c + 2);
        const int rem = nChunks - 1 - c;
        if (rem >= 2)      asm volatile("cp.async.wait_group 2;");
        else if (rem == 1) asm volatile("cp.async.wait_group 1;");
        else               asm volatile("cp.async.wait_group 0;");
        __syncthreads();

        const int buf = c % STAGES;
        const uint32_t aBase = sAu + (uint32_t)(buf * BM * LDS * 2);
        const uint32_t bBase = sBu + (uint32_t)(buf * TN * LDS * 2);
#pragma unroll
        for (int kk = 0; kk < BK; kk += 16) {
            uint32_t af[MT][4], bfr[NT][2];
#pragma unroll
            for (int mt = 0; mt < MT; mt++) {
                const int r = wr * WM + mt * 16;
                ldsm4(af[mt][0], af[mt][1], af[mt][2], af[mt][3],
                      aBase + (uint32_t)(((r + aRow) * LDS + kk + aCol) * 2));
            }
#pragma unroll
            for (int nt = 0; nt < NT; nt += 2) {
                const int n0 = wc * WN + nt * 8;
                ldsm4(bfr[nt][0], bfr[nt][1], bfr[nt + 1][0], bfr[nt + 1][1],
                      bBase + (uint32_t)(((n0 + bRow) * LDS + kk + bCol) * 2));
            }
#pragma unroll
            for (int mt = 0; mt < MT; mt++)
#pragma unroll
                for (int nt = 0; nt < NT; nt++)
                    MMA16816(acc[mt][nt], af[mt], bfr[nt]);
        }
        __syncthreads();
    }

    // epilogue
#pragma unroll
    for (int mt = 0; mt < MT; mt++) {
#pragma unroll
        for (int nt = 0; nt < NT; nt++) {
            const int rloc = wr * WM + mt * 16 + gid;
            const int cloc = wc * WN + nt * 8 + tig * 2;
            const int cg = col0 + cloc;
            float b0 = bias ? bias[cg] : 0.f;
            float b1 = bias ? bias[cg + 1] : 0.f;
#pragma unroll
            for (int half = 0; half < 2; half++) {
                const int rg = row0 + rloc + half * 8;
                float v0 = acc[mt][nt][half * 2 + 0] * scale + b0;
                float v1 = acc[mt][nt][half * 2 + 1] * scale + b1;
                if (act == 1) { v0 = fmaxf(v0, 0.f); v1 = fmaxf(v1, 0.f); }
                else if (act == 2) {
                    v0 = (v0 > 0.f) ? v0 : expm1f(v0);
                    v1 = (v1 > 0.f) ? v1 : expm1f(v1);
                }
                if (C)
                    *reinterpret_cast<float2*>(&C[(long)rg * ldc + cg]) = make_float2(v0, v1);
                if (C3) {
                    long base = (long)rg * ldc3 + cg;
                    *reinterpret_cast<__half2*>(&C3[base]) =
                        __halves2half2(__float2half_rn(v0), __float2half_rn(v1));
                    *reinterpret_cast<__half2*>(&C3[base + seg3]) =
                        __halves2half2(f16lo(v0), f16lo(v1));
                }
            }
        }
    }
}

// ---------------- fused softmax + attn@v (half-batch, fp16 operands) ----------------
__global__ __launch_bounds__(128)
void softmax_av(const float* __restrict__ s, const int* __restrict__ mask,
                const __half* __restrict__ v3t,
                __half* __restrict__ o3,
                float* __restrict__ probsOut, int headBase)
{
    constexpr int LDA = 136;    // pbuf: 64 rows x (128 K [hi64|lo64] + pad)
    constexpr int LDB = 520;    // vbuf: 32 rows x (512 hi + pad)
    extern __shared__ __half dsm[];
    __half* vbuf = dsm;
    __half* pbuf = dsm + 32 * LDB;
    __shared__ float rowm[64], rowinv[64];

    const int zz = blockIdx.z;
    const int g = headBase + zz;
    const int q0 = blockIdx.x * 64;
    const int mb = (g >> 3) * CN;
    const float* sbase = s + (long)zz * CN * CN;
    float* pout = probsOut ? probsOut + (long)zz * CN * CN : nullptr;
    const __half* vb = v3t + (long)g * 32 * 512;
    o3 += (long)(g >> 3) * ((long)CN * 512) + (g & 7) * 32;

    const int tid = threadIdx.x;
    const int w = tid >> 5, lane = tid & 31;
    const int gid = lane >> 2, tig = lane & 3;

    uint32_t vbu = (uint32_t)__cvta_generic_to_shared(vbuf);
    uint32_t pbu = (uint32_t)__cvta_generic_to_shared(pbuf);

#pragma unroll
    for (int i = 0; i < 16; i++) {
        const int idx = i * 128 + tid;
        const int r = idx >> 6, ch = idx & 63;
        cpa16(vbu + (uint32_t)((r * LDB + ch * 8) * 2), vb + r * 512 + ch * 8);
    }
    asm volatile("cp.async.commit_group;");

    for (int i = 0; i < 16; i++) {
        const int r = w * 16 + i;
        const float* srow = sbase + (long)(q0 + r) * CN;
        float mx = -1e30f;
        for (int j = lane; j < CN; j += 32)
            mx = fmaxf(mx, srow[j] + (float)mask[mb + j] * NEG_INF_F);
#pragma unroll
        for (int off = 16; off > 0; off >>= 1)
            mx = fmaxf(mx, __shfl_xor_sync(0xffffffffu, mx, off));
        float sum = 0.f;
        for (int j = lane; j < CN; j += 32)
            sum += __expf(srow[j] + (float)mask[mb + j] * NEG_INF_F - mx);
#pragma unroll
        for (int off = 16; off > 0; off >>= 1)
            sum += __shfl_xor_sync(0xffffffffu, sum, off);
        if (lane == 0) { rowm[r] = mx; rowinv[r] = 1.f / sum; }
    }
    asm volatile("cp.async.wait_group 0;");
    __syncthreads();

    const int aRow = lane & 15, aCol = (lane >> 4) << 3;
    const int bRow = ((lane >> 4) << 3) + (lane & 7), bCol = ((lane >> 3) & 1) << 3;

    float acc[4][4];
#pragma unroll
    for (int nt = 0; nt < 4; nt++)
#pragma unroll
        for (int i = 0; i < 4; i++) acc[nt][i] = 0.f;

    for (int jc = 0; jc < 8; jc++) {
#pragma unroll
        for (int i = 0; i < 16; i++) {
            const int r = w * 16 + i;
            const int j = jc * 64 + lane * 2;
            const float* sp = sbase + (long)(q0 + r) * CN + j;
            float2 v2 = *reinterpret_cast<const float2*>(sp);
            const float m = rowm[r], inv = rowinv[r];
            float p0 = __expf(v2.x + (float)mask[mb + j] * NEG_INF_F - m) * inv;
            float p1 = __expf(v2.y + (float)mask[mb + j + 1] * NEG_INF_F - m) * inv;
            if (pout)
                *reinterpret_cast<float2*>(&pout[(long)(q0 + r) * CN + j]) = make_float2(p0, p1);
            *reinterpret_cast<__half2*>(&pbuf[r * LDA + lane * 2]) =
                __halves2half2(__float2half_rn(p0), __float2half_rn(p1));
            *reinterpret_cast<__half2*>(&pbuf[r * LDA + 64 + lane * 2]) =
                __halves2half2(f16lo(p0), f16lo(p1));
        }
        __syncwarp();
        // 2 A-terms (hi, lo) share the same B tile columns jc*64..
#pragma unroll
        for (int kk = 0; kk < 64; kk += 16) {
            uint32_t bfr[4][2];
#pragma unroll
            for (int nt = 0; nt < 4; nt += 2) {
                const int n0 = nt * 8;
                ldsm4(bfr[nt][0], bfr[nt][1], bfr[nt + 1][0], bfr[nt + 1][1],
                      vbu + (uint32_t)(((n0 + bRow) * LDB + jc * 64 + kk + bCol) * 2));
            }
#pragma unroll
            for (int t2 = 0; t2 < 2; t2++) {
                uint32_t af[4];
                ldsm4(af[0], af[1], af[2], af[3],
                      pbu + (uint32_t)(((w * 16 + aRow) * LDA + t2 * 64 + kk + aCol) * 2));
#pragma unroll
                for (int nt = 0; nt < 4; nt++)
                    MMA16816(acc[nt], af, bfr[nt]);
            }
        }
        __syncwarp();
    }

#pragma unroll
    for (int nt = 0; nt < 4; nt++) {
        const int cg = nt * 8 + tig * 2;
#pragma unroll
        for (int half = 0; half < 2; half++) {
            const int rg = q0 + w * 16 + gid + half * 8;
            const float v0 = acc[nt][half * 2 + 0];
            const float v1 = acc[nt][half * 2 + 1];
            const long base = (long)rg * 512 + cg;
            *reinterpret_cast<__half2*>(&o3[base]) =
                __halves2half2(__float2half_rn(v0), __float2half_rn(v1));
            *reinterpret_cast<__half2*>(&o3[base + 256]) =
                __halves2half2(f16lo(v0), f16lo(v1));
        }
    }
}

// ---------------- fused weight split: src [R,C] fp32 -> dst [C,R] fp16 hi-only ----------------
struct WEnt { const float* src; __half* dst; int R; int C; int tiles; };
struct WTab { WEnt e[13]; };

__global__ void wsplit_all(WTab tab)
{
    __shared__ float tile[128][33];
    int bid = blockIdx.x;
    int i = 0;
    while (bid >= tab.e[i].tiles) { bid -= tab.e[i].tiles; i++; }
    const float* in = tab.e[i].src;
    __half* out = tab.e[i].dst;
    const int R = tab.e[i].R, C = tab.e[i].C;
    const int tC = C >> 5;
    const int r0 = (bid / tC) * 128, c0 = (bid % tC) * 32;

    for (int t = threadIdx.x; t < 128 * 32; t += 256) {
        int rr = t >> 5, cc = t & 31;
        tile[rr][cc] = in[(long)(r0 + rr) * C + c0 + cc];
    }
    __syncthreads();
    for (int t = threadIdx.x; t < 32 * 128; t += 256) {
        int cc = t >> 7, rr = t & 127;
        out[(long)(c0 + cc) * R + (r0 + rr)] = __float2half_rn(tile[rr][cc]);
    }
}

__global__ void pack_bias(const float* __restrict__ bq, const float* __restrict__ bk,
                          const float* __restrict__ bv, float* __restrict__ dst)
{
    const int l = blockIdx.x;
    const int d = threadIdx.x;
    float v;
    if (d < 256) v = bq[l * 256 + d];
    else if (d < 512) v = bk[l * 256 + d - 256];
    else v = bv[l * 256 + d - 512];
    dst[l * 768 + d] = v;
}

// ---------------- elementwise kernels ----------------

__global__ void embed_kernel(const int* __restrict__ node, const float* __restrict__ embed,
                             float* __restrict__ x, __half* __restrict__ x3)
{
    const int row = blockIdx.x;
    const int d = threadIdx.x;
    const float v = embed[(long)node[row] * CD + d];
    x[(long)row * CD + d] = v;
    x3[(long)row * 512 + d] = __float2half_rn(v);
    x3[(long)row * 512 + 256 + d] = f16lo(v);
}

// transpose hi-only: in [R,C] -> out [C,R] fp16
__global__ void tsplitB(const float* __restrict__ in, __half* __restrict__ out,
                        int irs, int R, long sIn1, long sIn2, int divIn, long sOut)
{
    __shared__ float tile[128][33];
    const long z = blockIdx.z;
    in  += (z / divIn) * sIn1 + (z % divIn) * sIn2;
    out += z * sOut;
    const int r0 = blockIdx.x * 128, c0 = blockIdx.y * 32;
    for (int i = threadIdx.x; i < 128 * 32; i += 256) {
        int rr = i >> 5, cc = i & 31;
        tile[rr][cc] = in[(long)(r0 + rr) * irs + c0 + cc];
    }
    __syncthreads();
    for (int i = threadIdx.x; i < 32 * 128; i += 256) {
        int cc = i >> 7, rr = i & 127;
        out[(long)(c0 + cc) * R + (r0 + rr)] = __float2half_rn(tile[rr][cc]);
    }
}

// q3 [hi|lo] (64/head), k3 hi-only (32/head)
__global__ void qk_split(const float* __restrict__ qkv,
                         __half* __restrict__ q3, __half* __restrict__ k3)
{
    const int row = blockIdx.x;
    const int b = row >> 9, i = row & 511;
    const int d = threadIdx.x;
    const int h = d >> 5, dd = d & 31;
    const long baseq = ((long)(b * CH + h) * CN + i) * 64;
    const long basek = ((long)(b * CH + h) * CN + i) * 32;
    float qv = qkv[(long)row * 768 + d];
    float kv = qkv[(long)row * 768 + 256 + d];
    q3[baseq + dd] = __float2half_rn(qv);
    q3[baseq + 32 + dd] = f16lo(qv);
    k3[basek + dd] = __float2half_rn(kv);
}

__global__ void e12_kernel(const float* __restrict__ h, const float* __restrict__ a1,
                           const float* __restrict__ a2, float* __restrict__ e1, float* __restrict__ e2)
{
    const int row = blockIdx.x;
    const int d = threadIdx.x;
    __shared__ float s1[256], s2[256];
    const float hv = h[(long)row * CD + d];
    s1[d] = hv * a1[d];
    s2[d] = hv * a2[d];
    __syncthreads();
    for (int off = 128; off > 0; off >>= 1) {
        if (d < off) { s1[d] += s1[d + off]; s2[d] += s2[d + off]; }
        __syncthreads();
    }
    if (d == 0) { e1[row] = s1[0]; e2[row] = s2[0]; }
}

__global__ void gat_softmax_kernel(const float* __restrict__ e1, const float* __restrict__ e2,
                                   const int* __restrict__ edge, __half* __restrict__ al3)
{
    const int row = blockIdx.x;
    const int b = row / CN;
    const int t = threadIdx.x;
    __shared__ float red[256];
    const float ei = e1[row];
    float vals[2];
#pragma unroll
    for (int p = 0; p < 2; p++) {
        const int j = t + p * 256;
        float e = ei + e2[b * CN + j];
        e = (e >= 0.f) ? e : 0.2f * e;
        vals[p] = (edge[(long)row * CN + j] > 0) ? e : NEG_INF_F;
    }
    red[t] = fmaxf(vals[0], vals[1]);
    __syncthreads();
    for (int off = 128; off > 0; off >>= 1) { if (t < off) red[t] = fmaxf(red[t], red[t + off]); __syncthreads(); }
    const float m = red[0];
    __syncthreads();
    float ex[2] = {__expf(vals[0] - m), __expf(vals[1] - m)};
    red[t] = ex[0] + ex[1];
    __syncthreads();
    for (int off = 128; off > 0; off >>= 1) { if (t < off) red[t] += red[t + off]; __syncthreads(); }
    const float inv = 1.f / red[0];
    const long b3 = (long)row * 1024;
#pragma unroll
    for (int p = 0; p < 2; p++) {
        const int j = t + p * 256;
        const float pr = ex[p] * inv;
        al3[b3 + j] = __float2half_rn(pr);
        al3[b3 + 512 + j] = f16lo(pr);
    }
}

__global__ void scale_pe_kernel(float* __restrict__ x, __half* __restrict__ x3)
{
    const int row = blockIdx.x;
    const int n = row % CN;
    const int d = threadIdx.x;
    const float expo = (2.0f * (float)(d >> 1)) / (float)CD;
    const float angle = (float)n * powf(10000.0f, -expo);
    const float pe = (d & 1) ? cosf(angle) : sinf(angle);
    const long idx = (long)row * CD + d;
    const float v = x[idx] * 16.0f + pe;
    x[idx] = v;
    x3[(long)row * 512 + d] = __float2half_rn(v);
    x3[(long)row * 512 + 256 + d] = f16lo(v);
}

__global__ void ln_kernel(const float* __restrict__ x, const float* __restrict__ delta,
                          const float* __restrict__ g, const float* __restrict__ bb,
                          float* __restrict__ out, __half* __restrict__ x3)
{
    const int row = blockIdx.x;
    const int d = threadIdx.x;
    __shared__ float red[256];
    const long idx = (long)row * CD + d;
    const float v = x[idx] + delta[idx];
    red[d] = v;
    __syncthreads();
    for (int off = 128; off > 0; off >>= 1) { if (d < off) red[d] += red[d + off]; __syncthreads(); }
    const float mu = red[0] * (1.0f / CD);
    __syncthreads();
    const float c = v - mu;
    red[d] = c * c;
    __syncthreads();
    for (int off = 128; off > 0; off >>= 1) { if (d < off) red[d] += red[d + off]; __syncthreads(); }
    const float var = red[0] * (1.0f / CD);
    const float r = c * rsqrtf(var + 1e-6f) * g[d] + bb[d];
    out[idx] = r;
    if (x3) {
        x3[(long)row * 512 + d] = __float2half_rn(r);
        x3[(long)row * 512 + 256 + d] = f16lo(r);
    }
}

// ---------------- host ----------------
struct G3 { __half* p; long s1; long s2; int ld; int seg; };

static void launch_gemm64(const __half* A, const __half* B, const float* bias, float* C,
                          int M, int N, int K3, int lda, int ldb, int ldc, int mapA, int mapB,
                          long sA, long sB, long sC1, long sC2, int divC,
                          float scale, int act, int batch, G3 g3)
{
    dim3 g(N / 64, M / 64, batch);
    size_t sm = 3 * (64 + 64) * 72 * 2;
    gemm_mma<64, 64, 64><<<g, 128, sm>>>(A, B, bias, C, lda, ldb, ldc, K3, mapA, mapB,
        sA, sB, sC1, sC2, divC, scale, act, g3.p, g3.s1, g3.s2, g3.ld, g3.seg);
}
static void launch_gemm32(const __half* A, const __half* B, float* C,
                          int M, int N, int K3, int lda, int ldb, int ldc, int mapA, int mapB,
                          long sA, long sB, long sC1, float scale, int batch)
{
    dim3 g(N / 64, M / 64, batch);
    size_t sm = 3 * (64 + 64) * 40 * 2;
    gemm_mma<64, 64, 32><<<g, 128, sm>>>(A, B, nullptr, C, lda, ldb, ldc, K3, mapA, mapB,
        sA, sB, sC1, 0, 1, scale, 0, nullptr, 0, 0, 0, 0);
}

extern "C" void kernel_launch(void* const* d_in, const int* in_sizes, int n_in,
                              void* d_out, int out_size)
{
    const int*   node  = (const int*)  d_in[0];
    const int*   edge  = (const int*)  d_in[1];
    const int*   mask  = (const int*)  d_in[2];
    const float* embed = (const float*)d_in[4];
    const float* Wg    = (const float*)d_in[5];
    const float* a1    = (const float*)d_in[6];
    const float* a2    = (const float*)d_in[7];
    const float* Wq    = (const float*)d_in[8];
    const float* bq    = (const float*)d_in[9];
    const float* Wk    = (const float*)d_in[10];
    const float* bk    = (const float*)d_in[11];
    const float* Wv    = (const float*)d_in[12];
    const float* bv    = (const float*)d_in[13];
    const float* Wo    = (const float*)d_in[14];
    const float* bo    = (const float*)d_in[15];
    const float* W1    = (const float*)d_in[16];
    const float* b1    = (const float*)d_in[17];
    const float* W2    = (const float*)d_in[18];
    const float* b2    = (const float*)d_in[19];
    const float* ln1g  = (const float*)d_in[20];
    const float* ln1b  = (const float*)d_in[21];
    const float* ln2g  = (const float*)d_in[22];
    const float* ln2b  = (const float*)d_in[23];

    cudaFuncSetAttribute((const void*)gemm_mma<64,64,64>, cudaFuncAttributeMaxDynamicSharedMemorySize, 60000);
    cudaFuncSetAttribute((const void*)gemm_mma<64,64,32>, cudaFuncAttributeMaxDynamicSharedMemorySize, 40000);
    cudaFuncSetAttribute((const void*)softmax_av, cudaFuncAttributeMaxDynamicSharedMemorySize, 70000);

    float *x, *h, *qkv, *t, *e1, *e2, *bias3, *sc;
    __half *x3, *o3, *ff3, *h3t, *al3, *q3, *k3, *v3t;
    __half *wg2, *wqkv2, *wo2, *w12, *w22;
    cudaGetSymbolAddress((void**)&x, g_x);     cudaGetSymbolAddress((void**)&h, g_h);
    cudaGetSymbolAddress((void**)&qkv, g_qkv); cudaGetSymbolAddress((void**)&t, g_t);
    cudaGetSymbolAddress((void**)&e1, g_e1);   cudaGetSymbolAddress((void**)&e2, g_e2);
    cudaGetSymbolAddress((void**)&bias3, g_bias);
    cudaGetSymbolAddress((void**)&sc, g_sc);
    cudaGetSymbolAddress((void**)&x3, g_x3);   cudaGetSymbolAddress((void**)&o3, g_o3);
    cudaGetSymbolAddress((void**)&ff3, g_ff3); cudaGetSymbolAddress((void**)&h3t, g_h3t);
    cudaGetSymbolAddress((void**)&al3, g_al3);
    cudaGetSymbolAddress((void**)&q3, g_q3);   cudaGetSymbolAddress((void**)&k3, g_k3);
    cudaGetSymbolAddress((void**)&v3t, g_v3t);
    cudaGetSymbolAddress((void**)&wg2, g_wg2); cudaGetSymbolAddress((void**)&wqkv2, g_wqkv2);
    cudaGetSymbolAddress((void**)&wo2, g_wo2); cudaGetSymbolAddress((void**)&w12, g_w12);
    cudaGetSymbolAddress((void**)&w22, g_w22);

    float* out_x    = (float*)d_out;
    float* out_attn = (float*)d_out + (long)CB * CN * CD;

    const int M = CB * CN;
    const long ND = (long)CN * CD;
    const float inv_sqrt_dh = 0.17677669529663687f;
    const G3 no3 = {nullptr, 0, 0, 0, 0};

    WTab tab;
    int nTiles = 0;
    auto add = [&](int i, const float* src, __half* dst, int R, int C) {
        tab.e[i] = {src, dst, R, C, (R / 128) * (C / 32)};
        nTiles += tab.e[i].tiles;
    };
    add(0, Wg, wg2, 256, 256);
    for (int l = 0; l < CL; l++) {
        const long w256 = (long)l * 65536, w1k = (long)l * 262144;
        add(1 + l * 6, Wq + w256, wqkv2 + (long)l * 768 * 256, 256, 256);
        add(2 + l * 6, Wk + w256, wqkv2 + (long)l * 768 * 256 + 256 * 256, 256, 256);
        add(3 + l * 6, Wv + w256, wqkv2 + (long)l * 768 * 256 + 512 * 256, 256, 256);
        add(4 + l * 6, Wo + w256, wo2 + (long)l * 256 * 256, 256, 256);
        add(5 + l * 6, W1 + w1k, w12 + (long)l * 1024 * 256, 256, 1024);
        add(6 + l * 6, W2 + w1k, w22 + (long)l * 256 * 1024, 1024, 256);
    }
    wsplit_all<<<nTiles, 256>>>(tab);
    pack_bias<<<CL, 768>>>(bq, bk, bv, bias3);

    embed_kernel<<<M, CD>>>(node, embed, x, x3);

    for (int hop = 0; hop < 2; hop++) {
        // h = x @ Wg : A=x3 [hi|lo] K3=512; B=wg2 hi-only mapB=256
        launch_gemm64(x3, wg2, nullptr, h, M, CD, 512, 512, 256, CD, 0, 256,
                      0, 0, 0, 0, 1, 1.f, 0, 1, no3);
        tsplitB<<<dim3(4, 8, CB), 256>>>(h, h3t, CD, CN, ND, 0, 1, (long)CD * 512);
        e12_kernel<<<M, CD>>>(h, a1, a2, e1, e2);
        gat_softmax_kernel<<<M, 256>>>(e1, e2, edge, al3);
        G3 gx3 = {x3, (long)CN * 512, 0, 512, 256};
        // x = elu(alpha@h): A=al3 [hi|lo] K3=1024; B=h3t hi-only mapB=512
        launch_gemm64(al3, h3t, nullptr, hop == 1 ? x : nullptr, CN, CD, 1024,
                      1024, 512, CD, 0, 512,
                      (long)CN * 1024, (long)CD * 512, ND, 0, 1, 1.f, 2, CB, gx3);
    }

    scale_pe_kernel<<<M, CD>>>(x, x3);

    for (int l = 0; l < CL; l++) {
        launch_gemm64(x3, wqkv2 + (long)l * 768 * 256, bias3 + l * 768, qkv,
                      M, 768, 512, 512, 256, 768, 0, 256,
                      0, 0, 0, 0, 1, 1.f, 0, 1, no3);

        qk_split<<<M, 256>>>(qkv, q3, k3);
        tsplitB<<<dim3(4, 1, CB * CH), 256>>>(qkv + 512, v3t, 768, CN,
                                              (long)CN * 768, 32, CH, 32L * 512);

        const bool last = (l == CL - 1);
        for (int half = 0; half < 2; half++) {
            const long qOff = (long)half * 64 * CN * 64;
            const long kOff = (long)half * 64 * CN * 32;
            // scores: A=q3 [hi|lo] K3=64; B=k3 hi-only mapB=32; BK=32
            launch_gemm32(q3 + qOff, k3 + kOff, sc, CN, CN, 64, 64, 32, CN, 0, 32,
                          (long)CN * 64, (long)CN * 32, (long)CN * CN,
                          inv_sqrt_dh, 64);
            softmax_av<<<dim3(8, 1, 64), 128, (32 * 520 + 64 * 136) * 2>>>(
                sc, mask, v3t, o3,
                last ? out_attn + (long)half * 64 * CN * CN : nullptr,
                half * 64);
        }

        launch_gemm64(o3, wo2 + (long)l * 256 * 256, bo + l * CD, t, M, CD, 512,
                      512, 256, CD, 0, 256,
                      0, 0, 0, 0, 1, 1.f, 0, 1, no3);
        ln_kernel<<<M, CD>>>(x, t, ln1g + l * CD, ln1b + l * CD, x, x3);

        G3 gff3 = {ff3, 0, 0, 2048, 1024};
        launch_gemm64(x3, w12 + (long)l * 1024 * 256, b1 + l * CDFF, nullptr,
                      M, CDFF, 512, 512, 256, CDFF, 0, 256,
                      0, 0, 0, 0, 1, 1.f, 1, 1, gff3);
        launch_gemm64(ff3, w22 + (long)l * 256 * 1024, b2 + l * CD, t, M, CD, 2048,
                      2048, 1024, CD, 0, 1024,
                      0, 0, 0, 0, 1, 1.f, 0, 1, no3);
        ln_kernel<<<M, CD>>>(x, t, ln2g + l * CD, ln2b + l * CD,
                             last ? out_x : x, last ? nullptr : x3);
    }
}

// round 16
// speedup vs baseline: 1.6758x; 1.2210x over previous
#include <cuda_runtime.h>
#include <cuda_fp16.h>
#include <math.h>
#include <stdint.h>

#define CB 16
#define CN 512
#define CD 256
#define CH 8
#define CDFF 1024
#define CL 2
#define NEG_INF_F (-1e9f)

// ---------------- scratch ----------------
static __device__ __align__(256) float g_x  [CB*CN*CD];
static __device__ __align__(256) float g_h  [CB*CN*CD];
static __device__ __align__(256) float g_qkv[CB*CN*768];
static __device__ __align__(256) float g_t  [CB*CN*CD];
static __device__ __align__(256) float g_e1 [CB*CN];
static __device__ __align__(256) float g_e2 [CB*CN];
static __device__ __align__(256) float g_bias[CL*768];
static __device__ __align__(256) float g_sc [64L*CN*CN];   // 67MB half-batch scores (L2-resident)

static __device__ __align__(256) __half g_x2  [CB*CN*256];
static __device__ __align__(256) __half g_o2  [CB*CN*256];
static __device__ __align__(256) __half g_ff2 [CB*CN*1024];
static __device__ __align__(256) __half g_h2t [CB*CD*512];
static __device__ __align__(256) __half g_al2 [CB*CN*512];
static __device__ __align__(256) __half g_q2  [CB*CH*CN*32];
static __device__ __align__(256) __half g_k2  [CB*CH*CN*32];
static __device__ __align__(256) __half g_v2t [CB*CH*32*512];
static __device__ __align__(256) __half g_wg2 [CD*256];
static __device__ __align__(256) __half g_wqkv2[CL*768*256];
static __device__ __align__(256) __half g_wo2 [CL*CD*256];
static __device__ __align__(256) __half g_w12 [CL*CDFF*256];
static __device__ __align__(256) __half g_w22 [CL*CD*1024];

__device__ __forceinline__ void cpa16(uint32_t s, const void* g) {
    asm volatile("cp.async.cg.shared.global [%0], [%1], 16;" :: "r"(s), "l"(g));
}
__device__ __forceinline__ void ldsm4(uint32_t& r0, uint32_t& r1, uint32_t& r2, uint32_t& r3, uint32_t addr) {
    asm volatile("ldmatrix.sync.aligned.m8n8.x4.shared.b16 {%0,%1,%2,%3}, [%4];"
                 : "=r"(r0), "=r"(r1), "=r"(r2), "=r"(r3) : "r"(addr));
}
#define MMA16816(acc, a, b) \
    asm volatile("mma.sync.aligned.m16n8k16.row.col.f32.f16.f16.f32 " \
                 "{%0,%1,%2,%3}, {%4,%5,%6,%7}, {%8,%9}, {%0,%1,%2,%3};" \
                 : "+f"((acc)[0]), "+f"((acc)[1]), "+f"((acc)[2]), "+f"((acc)[3]) \
                 : "r"((a)[0]), "r"((a)[1]), "r"((a)[2]), "r"((a)[3]), \
                   "r"((b)[0]), "r"((b)[1]))

// ---------------- 3-stage cp.async mma.sync fp16 GEMM, C nullable, fp16 C2 side output ----------------
template<int BM, int TN, int BK>
__global__ __launch_bounds__((BM/32)*(TN/32)*32)
void gemm_mma(const __half* __restrict__ A, const __half* __restrict__ B,
              const float* __restrict__ bias, float* __restrict__ C,
              int lda, int ldb, int ldc, int K,
              long strA, long strB, long sC1, long sC2, int divC,
              float scale, int act,
              __half* __restrict__ C2, long sC21, long sC22, int ldc2)
{
    constexpr int WM = 32, WN = 32;
    constexpr int LDS = BK + 8;
    constexpr int MT = 2, NT = 4;
    constexpr int WCOLS = TN / WN;
    constexpr int THREADS = (BM / WM) * (TN / WN) * 32;
    constexpr int AITERS = BM * (BK / 8) / THREADS;
    constexpr int BITERS = TN * (BK / 8) / THREADS;
    constexpr int STAGES = 3;

    extern __shared__ __half smem[];
    __half* sA = smem;
    __half* sB = smem + STAGES * BM * LDS;

    const long z = blockIdx.z;
    A += z * strA;
    B += z * strB;
    if (C)  C  += (z / divC) * sC1 + (z % divC) * sC2;
    if (C2) C2 += (z / divC) * sC21 + (z % divC) * sC22;
    const int row0 = blockIdx.y * BM;
    const int col0 = blockIdx.x * TN;

    const int tid = threadIdx.x;
    const int w = tid >> 5, lane = tid & 31;
    const int wr = w / WCOLS, wc = w % WCOLS;
    const int gid = lane >> 2, tig = lane & 3;

    uint32_t sAu = (uint32_t)__cvta_generic_to_shared(sA);
    uint32_t sBu = (uint32_t)__cvta_generic_to_shared(sB);

    const int aRow = lane & 15, aCol = (lane >> 4) << 3;
    const int bRow = ((lane >> 4) << 3) + (lane & 7), bCol = ((lane >> 3) & 1) << 3;

    float acc[MT][NT][4];
#pragma unroll
    for (int mt = 0; mt < MT; mt++)
#pragma unroll
        for (int nt = 0; nt < NT; nt++)
#pragma unroll
            for (int i = 0; i < 4; i++) acc[mt][nt][i] = 0.f;

    const int nChunks = K / BK;

    auto issue = [&](int s) {
        const int buf = s % STAGES;
        const int k0 = s * BK;
#pragma unroll
        for (int i = 0; i < AITERS; i++) {
            const int idx = i * THREADS + tid;
            const int r = idx / (BK / 8), kc = (idx % (BK / 8)) * 8;
            cpa16(sAu + (uint32_t)(((buf * BM + r) * LDS + kc) * 2),
                  A + (long)(row0 + r) * lda + k0 + kc);
        }
#pragma unroll
        for (int i = 0; i < BITERS; i++) {
            const int idx = i * THREADS + tid;
            const int r = idx / (BK / 8), kc = (idx % (BK / 8)) * 8;
            cpa16(sBu + (uint32_t)(((buf * TN + r) * LDS + kc) * 2),
                  B + (long)(col0 + r) * ldb + k0 + kc);
        }
        asm volatile("cp.async.commit_group;");
    };

    issue(0);
    if (nChunks > 1) issue(1);
    for (int c = 0; c < nChunks; c++) {
        if (c + 2 < nChunks) issue(c + 2);
        const int rem = nChunks - 1 - c;
        if (rem >= 2)      asm volatile("cp.async.wait_group 2;");
        else if (rem == 1) asm volatile("cp.async.wait_group 1;");
        else               asm volatile("cp.async.wait_group 0;");
        __syncthreads();

        const int buf = c % STAGES;
        const uint32_t aBase = sAu + (uint32_t)(buf * BM * LDS * 2);
        const uint32_t bBase = sBu + (uint32_t)(buf * TN * LDS * 2);
#pragma unroll
        for (int kk = 0; kk < BK; kk += 16) {
            uint32_t af[MT][4], bfr[NT][2];
#pragma unroll
            for (int mt = 0; mt < MT; mt++) {
                const int r = wr * WM + mt * 16;
                ldsm4(af[mt][0], af[mt][1], af[mt][2], af[mt][3],
                      aBase + (uint32_t)(((r + aRow) * LDS + kk + aCol) * 2));
            }
#pragma unroll
            for (int nt = 0; nt < NT; nt += 2) {
                const int n0 = wc * WN + nt * 8;
                ldsm4(bfr[nt][0], bfr[nt][1], bfr[nt + 1][0], bfr[nt + 1][1],
                      bBase + (uint32_t)(((n0 + bRow) * LDS + kk + bCol) * 2));
            }
#pragma unroll
            for (int mt = 0; mt < MT; mt++)
#pragma unroll
                for (int nt = 0; nt < NT; nt++)
                    MMA16816(acc[mt][nt], af[mt], bfr[nt]);
        }
        __syncthreads();
    }

    // epilogue
#pragma unroll
    for (int mt = 0; mt < MT; mt++) {
#pragma unroll
        for (int nt = 0; nt < NT; nt++) {
            const int rloc = wr * WM + mt * 16 + gid;
            const int cloc = wc * WN + nt * 8 + tig * 2;
            const int cg = col0 + cloc;
            float b0 = bias ? bias[cg] : 0.f;
            float b1 = bias ? bias[cg + 1] : 0.f;
#pragma unroll
            for (int half = 0; half < 2; half++) {
                const int rg = row0 + rloc + half * 8;
                float v0 = acc[mt][nt][half * 2 + 0] * scale + b0;
                float v1 = acc[mt][nt][half * 2 + 1] * scale + b1;
                if (act == 1) { v0 = fmaxf(v0, 0.f); v1 = fmaxf(v1, 0.f); }
                else if (act == 2) {
                    v0 = (v0 > 0.f) ? v0 : expm1f(v0);
                    v1 = (v1 > 0.f) ? v1 : expm1f(v1);
                }
                if (C)
                    *reinterpret_cast<float2*>(&C[(long)rg * ldc + cg]) = make_float2(v0, v1);
                if (C2)
                    *reinterpret_cast<__half2*>(&C2[(long)rg * ldc2 + cg]) =
                        __halves2half2(__float2half_rn(v0), __float2half_rn(v1));
            }
        }
    }
}

// ---------------- fused softmax + attn@v (half-batch, fp16 hi-only) ----------------
__global__ __launch_bounds__(128)
void softmax_av(const float* __restrict__ s, const int* __restrict__ mask,
                const __half* __restrict__ v2t,
                __half* __restrict__ o2,
                float* __restrict__ probsOut, int headBase)
{
    constexpr int LDA = 72;     // pbuf: 64 rows x (64 + pad)
    constexpr int LDB = 520;    // vbuf: 32 rows x (512 + pad)
    extern __shared__ __half dsm[];
    __half* vbuf = dsm;
    __half* pbuf = dsm + 32 * LDB;
    __shared__ float rowm[64], rowinv[64];

    const int zz = blockIdx.z;
    const int g = headBase + zz;
    const int q0 = blockIdx.x * 64;
    const int mb = (g >> 3) * CN;
    const float* sbase = s + (long)zz * CN * CN;
    float* pout = probsOut ? probsOut + (long)zz * CN * CN : nullptr;
    const __half* vb = v2t + (long)g * 32 * 512;
    o2 += (long)(g >> 3) * ((long)CN * 256) + (g & 7) * 32;

    const int tid = threadIdx.x;
    const int w = tid >> 5, lane = tid & 31;
    const int gid = lane >> 2, tig = lane & 3;

    uint32_t vbu = (uint32_t)__cvta_generic_to_shared(vbuf);
    uint32_t pbu = (uint32_t)__cvta_generic_to_shared(pbuf);

#pragma unroll
    for (int i = 0; i < 16; i++) {
        const int idx = i * 128 + tid;
        const int r = idx >> 6, ch = idx & 63;
        cpa16(vbu + (uint32_t)((r * LDB + ch * 8) * 2), vb + r * 512 + ch * 8);
    }
    asm volatile("cp.async.commit_group;");

    for (int i = 0; i < 16; i++) {
        const int r = w * 16 + i;
        const float* srow = sbase + (long)(q0 + r) * CN;
        float mx = -1e30f;
        for (int j = lane; j < CN; j += 32)
            mx = fmaxf(mx, srow[j] + (float)mask[mb + j] * NEG_INF_F);
#pragma unroll
        for (int off = 16; off > 0; off >>= 1)
            mx = fmaxf(mx, __shfl_xor_sync(0xffffffffu, mx, off));
        float sum = 0.f;
        for (int j = lane; j < CN; j += 32)
            sum += __expf(srow[j] + (float)mask[mb + j] * NEG_INF_F - mx);
#pragma unroll
        for (int off = 16; off > 0; off >>= 1)
            sum += __shfl_xor_sync(0xffffffffu, sum, off);
        if (lane == 0) { rowm[r] = mx; rowinv[r] = 1.f / sum; }
    }
    asm volatile("cp.async.wait_group 0;");
    __syncthreads();

    const int aRow = lane & 15, aCol = (lane >> 4) << 3;
    const int bRow = ((lane >> 4) << 3) + (lane & 7), bCol = ((lane >> 3) & 1) << 3;

    float acc[4][4];
#pragma unroll
    for (int nt = 0; nt < 4; nt++)
#pragma unroll
        for (int i = 0; i < 4; i++) acc[nt][i] = 0.f;

    for (int jc = 0; jc < 8; jc++) {
#pragma unroll
        for (int i = 0; i < 16; i++) {
            const int r = w * 16 + i;
            const int j = jc * 64 + lane * 2;
            const float* sp = sbase + (long)(q0 + r) * CN + j;
            float2 v2 = *reinterpret_cast<const float2*>(sp);
            const float m = rowm[r], inv = rowinv[r];
            float p0 = __expf(v2.x + (float)mask[mb + j] * NEG_INF_F - m) * inv;
            float p1 = __expf(v2.y + (float)mask[mb + j + 1] * NEG_INF_F - m) * inv;
            if (pout)
                *reinterpret_cast<float2*>(&pout[(long)(q0 + r) * CN + j]) = make_float2(p0, p1);
            *reinterpret_cast<__half2*>(&pbuf[r * LDA + lane * 2]) =
                __halves2half2(__float2half_rn(p0), __float2half_rn(p1));
        }
        __syncwarp();
#pragma unroll
        for (int kk = 0; kk < 64; kk += 16) {
            uint32_t af[4];
            ldsm4(af[0], af[1], af[2], af[3],
                  pbu + (uint32_t)(((w * 16 + aRow) * LDA + kk + aCol) * 2));
            uint32_t bfr[4][2];
#pragma unroll
            for (int nt = 0; nt < 4; nt += 2) {
                const int n0 = nt * 8;
                ldsm4(bfr[nt][0], bfr[nt][1], bfr[nt + 1][0], bfr[nt + 1][1],
                      vbu + (uint32_t)(((n0 + bRow) * LDB + jc * 64 + kk + bCol) * 2));
            }
#pragma unroll
            for (int nt = 0; nt < 4; nt++)
                MMA16816(acc[nt], af, bfr[nt]);
        }
        __syncwarp();
    }

#pragma unroll
    for (int nt = 0; nt < 4; nt++) {
        const int cg = nt * 8 + tig * 2;
#pragma unroll
        for (int half = 0; half < 2; half++) {
            const int rg = q0 + w * 16 + gid + half * 8;
            *reinterpret_cast<__half2*>(&o2[(long)rg * 256 + cg]) =
                __halves2half2(__float2half_rn(acc[nt][half * 2 + 0]),
                               __float2half_rn(acc[nt][half * 2 + 1]));
        }
    }
}

// ---------------- fused weight convert: src [R,C] fp32 -> dst [C,R] fp16 ----------------
struct WEnt { const float* src; __half* dst; int R; int C; int tiles; };
struct WTab { WEnt e[13]; };

__global__ void wsplit_all(WTab tab)
{
    __shared__ float tile[128][33];
    int bid = blockIdx.x;
    int i = 0;
    while (bid >= tab.e[i].tiles) { bid -= tab.e[i].tiles; i++; }
    const float* in = tab.e[i].src;
    __half* out = tab.e[i].dst;
    const int R = tab.e[i].R, C = tab.e[i].C;
    const int tC = C >> 5;
    const int r0 = (bid / tC) * 128, c0 = (bid % tC) * 32;

    for (int t = threadIdx.x; t < 128 * 32; t += 256) {
        int rr = t >> 5, cc = t & 31;
        tile[rr][cc] = in[(long)(r0 + rr) * C + c0 + cc];
    }
    __syncthreads();
    for (int t = threadIdx.x; t < 32 * 128; t += 256) {
        int cc = t >> 7, rr = t & 127;
        out[(long)(c0 + cc) * R + (r0 + rr)] = __float2half_rn(tile[rr][cc]);
    }
}

__global__ void pack_bias(const float* __restrict__ bq, const float* __restrict__ bk,
                          const float* __restrict__ bv, float* __restrict__ dst)
{
    const int l = blockIdx.x;
    const int d = threadIdx.x;
    float v;
    if (d < 256) v = bq[l * 256 + d];
    else if (d < 512) v = bk[l * 256 + d - 256];
    else v = bv[l * 256 + d - 512];
    dst[l * 768 + d] = v;
}

// ---------------- elementwise kernels ----------------

__global__ void embed_kernel(const int* __restrict__ node, const float* __restrict__ embed,
                             float* __restrict__ x, __half* __restrict__ x2)
{
    const int row = blockIdx.x;
    const int d = threadIdx.x;
    const float v = embed[(long)node[row] * CD + d];
    x[(long)row * CD + d] = v;
    x2[(long)row * 256 + d] = __float2half_rn(v);
}

__global__ void tsplitB(const float* __restrict__ in, __half* __restrict__ out,
                        int irs, int R, long sIn1, long sIn2, int divIn, long sOut)
{
    __shared__ float tile[128][33];
    const long z = blockIdx.z;
    in  += (z / divIn) * sIn1 + (z % divIn) * sIn2;
    out += z * sOut;
    const int r0 = blockIdx.x * 128, c0 = blockIdx.y * 32;
    for (int i = threadIdx.x; i < 128 * 32; i += 256) {
        int rr = i >> 5, cc = i & 31;
        tile[rr][cc] = in[(long)(r0 + rr) * irs + c0 + cc];
    }
    __syncthreads();
    for (int i = threadIdx.x; i < 32 * 128; i += 256) {
        int cc = i >> 7, rr = i & 127;
        out[(long)(c0 + cc) * R + (r0 + rr)] = __float2half_rn(tile[rr][cc]);
    }
}

__global__ void qk_split(const float* __restrict__ qkv,
                         __half* __restrict__ q2, __half* __restrict__ k2)
{
    const int row = blockIdx.x;
    const int b = row >> 9, i = row & 511;
    const int d = threadIdx.x;
    const int h = d >> 5, dd = d & 31;
    const long base = ((long)(b * CH + h) * CN + i) * 32;
    q2[base + dd] = __float2half_rn(qkv[(long)row * 768 + d]);
    k2[base + dd] = __float2half_rn(qkv[(long)row * 768 + 256 + d]);
}

__global__ void e12_kernel(const float* __restrict__ h, const float* __restrict__ a1,
                           const float* __restrict__ a2, float* __restrict__ e1, float* __restrict__ e2)
{
    const int row = blockIdx.x;
    const int d = threadIdx.x;
    __shared__ float s1[256], s2[256];
    const float hv = h[(long)row * CD + d];
    s1[d] = hv * a1[d];
    s2[d] = hv * a2[d];
    __syncthreads();
    for (int off = 128; off > 0; off >>= 1) {
        if (d < off) { s1[d] += s1[d + off]; s2[d] += s2[d + off]; }
        __syncthreads();
    }
    if (d == 0) { e1[row] = s1[0]; e2[row] = s2[0]; }
}

__global__ void gat_softmax_kernel(const float* __restrict__ e1, const float* __restrict__ e2,
                                   const int* __restrict__ edge, __half* __restrict__ al2)
{
    const int row = blockIdx.x;
    const int b = row / CN;
    const int t = threadIdx.x;
    __shared__ float red[256];
    const float ei = e1[row];
    float vals[2];
#pragma unroll
    for (int p = 0; p < 2; p++) {
        const int j = t + p * 256;
        float e = ei + e2[b * CN + j];
        e = (e >= 0.f) ? e : 0.2f * e;
        vals[p] = (edge[(long)row * CN + j] > 0) ? e : NEG_INF_F;
    }
    red[t] = fmaxf(vals[0], vals[1]);
    __syncthreads();
    for (int off = 128; off > 0; off >>= 1) { if (t < off) red[t] = fmaxf(red[t], red[t + off]); __syncthreads(); }
    const float m = red[0];
    __syncthreads();
    float ex[2] = {__expf(vals[0] - m), __expf(vals[1] - m)};
    red[t] = ex[0] + ex[1];
    __syncthreads();
    for (int off = 128; off > 0; off >>= 1) { if (t < off) red[t] += red[t + off]; __syncthreads(); }
    const float inv = 1.f / red[0];
    const long b2 = (long)row * 512;
#pragma unroll
    for (int p = 0; p < 2; p++) {
        const int j = t + p * 256;
        al2[b2 + j] = __float2half_rn(ex[p] * inv);
    }
}

__global__ void scale_pe_kernel(float* __restrict__ x, __half* __restrict__ x2)
{
    const int row = blockIdx.x;
    const int n = row % CN;
    const int d = threadIdx.x;
    const float expo = (2.0f * (float)(d >> 1)) / (float)CD;
    const float angle = (float)n * powf(10000.0f, -expo);
    const float pe = (d & 1) ? cosf(angle) : sinf(angle);
    const long idx = (long)row * CD + d;
    const float v = x[idx] * 16.0f + pe;
    x[idx] = v;
    x2[(long)row * 256 + d] = __float2half_rn(v);
}

__global__ void ln_kernel(const float* __restrict__ x, const float* __restrict__ delta,
                          const float* __restrict__ g, const float* __restrict__ bb,
                          float* __restrict__ out, __half* __restrict__ x2)
{
    const int row = blockIdx.x;
    const int d = threadIdx.x;
    __shared__ float red[256];
    const long idx = (long)row * CD + d;
    const float v = x[idx] + delta[idx];
    red[d] = v;
    __syncthreads();
    for (int off = 128; off > 0; off >>= 1) { if (d < off) red[d] += red[d + off]; __syncthreads(); }
    const float mu = red[0] * (1.0f / CD);
    __syncthreads();
    const float c = v - mu;
    red[d] = c * c;
    __syncthreads();
    for (int off = 128; off > 0; off >>= 1) { if (d < off) red[d] += red[d + off]; __syncthreads(); }
    const float var = red[0] * (1.0f / CD);
    const float r = c * rsqrtf(var + 1e-6f) * g[d] + bb[d];
    out[idx] = r;
    if (x2) x2[(long)row * 256 + d] = __float2half_rn(r);
}

// ---------------- host ----------------
struct G2 { __half* p; long s1; long s2; int ld; };

static void launch_gemm64(const __half* A, const __half* B, const float* bias, float* C,
                          int M, int N, int K, int lda, int ldb, int ldc,
                          long sA, long sB, long sC1, long sC2, int divC,
                          float scale, int act, int batch, G2 g2)
{
    dim3 g(N / 64, M / 64, batch);
    size_t sm = 3 * (64 + 64) * 72 * 2;
    gemm_mma<64, 64, 64><<<g, 128, sm>>>(A, B, bias, C, lda, ldb, ldc, K,
        sA, sB, sC1, sC2, divC, scale, act, g2.p, g2.s1, g2.s2, g2.ld);
}
static void launch_gemm32(const __half* A, const __half* B, float* C,
                          int M, int N, int K, int lda, int ldb, int ldc,
                          long sA, long sB, long sC1, float scale, int batch)
{
    dim3 g(N / 64, M / 64, batch);
    size_t sm = 3 * (64 + 64) * 40 * 2;
    gemm_mma<64, 64, 32><<<g, 128, sm>>>(A, B, nullptr, C, lda, ldb, ldc, K,
        sA, sB, sC1, 0, 1, scale, 0, nullptr, 0, 0, 0);
}

extern "C" void kernel_launch(void* const* d_in, const int* in_sizes, int n_in,
                              void* d_out, int out_size)
{
    const int*   node  = (const int*)  d_in[0];
    const int*   edge  = (const int*)  d_in[1];
    const int*   mask  = (const int*)  d_in[2];
    const float* embed = (const float*)d_in[4];
    const float* Wg    = (const float*)d_in[5];
    const float* a1    = (const float*)d_in[6];
    const float* a2    = (const float*)d_in[7];
    const float* Wq    = (const float*)d_in[8];
    const float* bq    = (const float*)d_in[9];
    const float* Wk    = (const float*)d_in[10];
    const float* bk    = (const float*)d_in[11];
    const float* Wv    = (const float*)d_in[12];
    const float* bv    = (const float*)d_in[13];
    const float* Wo    = (const float*)d_in[14];
    const float* bo    = (const float*)d_in[15];
    const float* W1    = (const float*)d_in[16];
    const float* b1    = (const float*)d_in[17];
    const float* W2    = (const float*)d_in[18];
    const float* b2    = (const float*)d_in[19];
    const float* ln1g  = (const float*)d_in[20];
    const float* ln1b  = (const float*)d_in[21];
    const float* ln2g  = (const float*)d_in[22];
    const float* ln2b  = (const float*)d_in[23];

    cudaFuncSetAttribute((const void*)gemm_mma<64,64,64>, cudaFuncAttributeMaxDynamicSharedMemorySize, 60000);
    cudaFuncSetAttribute((const void*)gemm_mma<64,64,32>, cudaFuncAttributeMaxDynamicSharedMemorySize, 40000);
    cudaFuncSetAttribute((const void*)softmax_av, cudaFuncAttributeMaxDynamicSharedMemorySize, 50000);

    float *x, *h, *qkv, *t, *e1, *e2, *bias3, *sc;
    __half *x2, *o2, *ff2, *h2t, *al2, *q2, *k2, *v2t;
    __half *wg2, *wqkv2, *wo2, *w12, *w22;
    cudaGetSymbolAddress((void**)&x, g_x);     cudaGetSymbolAddress((void**)&h, g_h);
    cudaGetSymbolAddress((void**)&qkv, g_qkv); cudaGetSymbolAddress((void**)&t, g_t);
    cudaGetSymbolAddress((void**)&e1, g_e1);   cudaGetSymbolAddress((void**)&e2, g_e2);
    cudaGetSymbolAddress((void**)&bias3, g_bias);
    cudaGetSymbolAddress((void**)&sc, g_sc);
    cudaGetSymbolAddress((void**)&x2, g_x2);   cudaGetSymbolAddress((void**)&o2, g_o2);
    cudaGetSymbolAddress((void**)&ff2, g_ff2); cudaGetSymbolAddress((void**)&h2t, g_h2t);
    cudaGetSymbolAddress((void**)&al2, g_al2);
    cudaGetSymbolAddress((void**)&q2, g_q2);   cudaGetSymbolAddress((void**)&k2, g_k2);
    cudaGetSymbolAddress((void**)&v2t, g_v2t);
    cudaGetSymbolAddress((void**)&wg2, g_wg2); cudaGetSymbolAddress((void**)&wqkv2, g_wqkv2);
    cudaGetSymbolAddress((void**)&wo2, g_wo2); cudaGetSymbolAddress((void**)&w12, g_w12);
    cudaGetSymbolAddress((void**)&w22, g_w22);

    float* out_x    = (float*)d_out;
    float* out_attn = (float*)d_out + (long)CB * CN * CD;

    const int M = CB * CN;
    const long ND = (long)CN * CD;
    const float inv_sqrt_dh = 0.17677669529663687f;
    const G2 no2 = {nullptr, 0, 0, 0};

    WTab tab;
    int nTiles = 0;
    auto add = [&](int i, const float* src, __half* dst, int R, int C) {
        tab.e[i] = {src, dst, R, C, (R / 128) * (C / 32)};
        nTiles += tab.e[i].tiles;
    };
    add(0, Wg, wg2, 256, 256);
    for (int l = 0; l < CL; l++) {
        const long w256 = (long)l * 65536, w1k = (long)l * 262144;
        add(1 + l * 6, Wq + w256, wqkv2 + (long)l * 768 * 256, 256, 256);
        add(2 + l * 6, Wk + w256, wqkv2 + (long)l * 768 * 256 + 256 * 256, 256, 256);
        add(3 + l * 6, Wv + w256, wqkv2 + (long)l * 768 * 256 + 512 * 256, 256, 256);
        add(4 + l * 6, Wo + w256, wo2 + (long)l * 256 * 256, 256, 256);
        add(5 + l * 6, W1 + w1k, w12 + (long)l * 1024 * 256, 256, 1024);
        add(6 + l * 6, W2 + w1k, w22 + (long)l * 256 * 1024, 1024, 256);
    }
    wsplit_all<<<nTiles, 256>>>(tab);
    pack_bias<<<CL, 768>>>(bq, bk, bv, bias3);

    embed_kernel<<<M, CD>>>(node, embed, x, x2);

    for (int hop = 0; hop < 2; hop++) {
        // h = x @ Wg : K=256
        launch_gemm64(x2, wg2, nullptr, h, M, CD, 256, 256, 256, CD,
                      0, 0, 0, 0, 1, 1.f, 0, 1, no2);
        tsplitB<<<dim3(4, 8, CB), 256>>>(h, h2t, CD, CN, ND, 0, 1, (long)CD * 512);
        e12_kernel<<<M, CD>>>(h, a1, a2, e1, e2);
        gat_softmax_kernel<<<M, 256>>>(e1, e2, edge, al2);
        G2 gx2 = {x2, (long)CN * 256, 0, 256};
        // x = elu(alpha@h): K=512
        launch_gemm64(al2, h2t, nullptr, hop == 1 ? x : nullptr, CN, CD, 512,
                      512, 512, CD,
                      (long)CN * 512, (long)CD * 512, ND, 0, 1, 1.f, 2, CB, gx2);
    }

    scale_pe_kernel<<<M, CD>>>(x, x2);

    for (int l = 0; l < CL; l++) {
        launch_gemm64(x2, wqkv2 + (long)l * 768 * 256, bias3 + l * 768, qkv,
                      M, 768, 256, 256, 256, 768,
                      0, 0, 0, 0, 1, 1.f, 0, 1, no2);

        qk_split<<<M, 256>>>(qkv, q2, k2);
        tsplitB<<<dim3(4, 1, CB * CH), 256>>>(qkv + 512, v2t, 768, CN,
                                              (long)CN * 768, 32, CH, 32L * 512);

        const bool last = (l == CL - 1);
        for (int half = 0; half < 2; half++) {
            const long qkOff = (long)half * 64 * CN * 32;
            // scores: K=32, single chunk
            launch_gemm32(q2 + qkOff, k2 + qkOff, sc, CN, CN, 32, 32, 32, CN,
                          (long)CN * 32, (long)CN * 32, (long)CN * CN,
                          inv_sqrt_dh, 64);
            softmax_av<<<dim3(8, 1, 64), 128, (32 * 520 + 64 * 72) * 2>>>(
                sc, mask, v2t, o2,
                last ? out_attn + (long)half * 64 * CN * CN : nullptr,
                half * 64);
        }

        launch_gemm64(o2, wo2 + (long)l * 256 * 256, bo + l * CD, t, M, CD, 256,
                      256, 256, CD,
                      0, 0, 0, 0, 1, 1.f, 0, 1, no2);
        ln_kernel<<<M, CD>>>(x, t, ln1g + l * CD, ln1b + l * CD, x, x2);

        G2 gff2 = {ff2, 0, 0, 1024};
        launch_gemm64(x2, w12 + (long)l * 1024 * 256, b1 + l * CDFF, nullptr,
                      M, CDFF, 256, 256, 256, CDFF,
                      0, 0, 0, 0, 1, 1.f, 1, 1, gff2);
        launch_gemm64(ff2, w22 + (long)l * 256 * 1024, b2 + l * CD, t, M, CD, 1024,
                      1024, 1024, CD,
                      0, 0, 0, 0, 1, 1.f, 0, 1, no2);
        ln_kernel<<<M, CD>>>(x, t, ln2g + l * CD, ln2b + l * CD,
                             last ? out_x : x, last ? nullptr : x2);
    }
}

// round 17
// speedup vs baseline: 1.7294x; 1.0320x over previous
#include <cuda_runtime.h>
#include <cuda_fp16.h>
#include <math.h>
#include <stdint.h>

#define CB 16
#define CN 512
#define CD 256
#define CH 8
#define CDFF 1024
#define CL 2
#define NEG_INF_F (-1e9f)

// ---------------- scratch ----------------
static __device__ __align__(256) float g_x  [CB*CN*CD];
static __device__ __align__(256) float g_h  [CB*CN*CD];
static __device__ __align__(256) float g_t  [CB*CN*CD];
static __device__ __align__(256) float g_e1 [CB*CN];
static __device__ __align__(256) float g_e2 [CB*CN];
static __device__ __align__(256) float g_bias[CL*768];
static __device__ __align__(256) float g_sc [64L*CN*CN];   // 67MB half-batch scores (L2-resident)

static __device__ __align__(256) __half g_qkv2[CB*CN*768];
static __device__ __align__(256) __half g_x2  [CB*CN*256];
static __device__ __align__(256) __half g_o2  [CB*CN*256];
static __device__ __align__(256) __half g_ff2 [CB*CN*1024];
static __device__ __align__(256) __half g_h2t [CB*CD*512];
static __device__ __align__(256) __half g_al2 [CB*CN*512];
static __device__ __align__(256) __half g_v2t [CB*CH*32*512];
static __device__ __align__(256) __half g_wg2 [CD*256];
static __device__ __align__(256) __half g_wqkv2[CL*768*256];
static __device__ __align__(256) __half g_wo2 [CL*CD*256];
static __device__ __align__(256) __half g_w12 [CL*CDFF*256];
static __device__ __align__(256) __half g_w22 [CL*CD*1024];

__device__ __forceinline__ void cpa16(uint32_t s, const void* g) {
    asm volatile("cp.async.cg.shared.global [%0], [%1], 16;" :: "r"(s), "l"(g));
}
__device__ __forceinline__ void ldsm4(uint32_t& r0, uint32_t& r1, uint32_t& r2, uint32_t& r3, uint32_t addr) {
    asm volatile("ldmatrix.sync.aligned.m8n8.x4.shared.b16 {%0,%1,%2,%3}, [%4];"
                 : "=r"(r0), "=r"(r1), "=r"(r2), "=r"(r3) : "r"(addr));
}
#define MMA16816(acc, a, b) \
    asm volatile("mma.sync.aligned.m16n8k16.row.col.f32.f16.f16.f32 " \
                 "{%0,%1,%2,%3}, {%4,%5,%6,%7}, {%8,%9}, {%0,%1,%2,%3};" \
                 : "+f"((acc)[0]), "+f"((acc)[1]), "+f"((acc)[2]), "+f"((acc)[3]) \
                 : "r"((a)[0]), "r"((a)[1]), "r"((a)[2]), "r"((a)[3]), \
                   "r"((b)[0]), "r"((b)[1]))

// ---------------- 3-stage cp.async mma.sync fp16 GEMM, generalized batch offsets ----------------
template<int BM, int TN, int BK>
__global__ __launch_bounds__((BM/32)*(TN/32)*32)
void gemm_mma(const __half* __restrict__ A, const __half* __restrict__ B,
              const float* __restrict__ bias, float* __restrict__ C,
              int lda, int ldb, int ldc, int K,
              long sA1, long sA2, int divA,
              long sB1, long sB2, int divB,
              long sC1, long sC2, int divC,
              float scale, int act,
              __half* __restrict__ C2, long sC21, long sC22, int ldc2)
{
    constexpr int WM = 32, WN = 32;
    constexpr int LDS = BK + 8;
    constexpr int MT = 2, NT = 4;
    constexpr int WCOLS = TN / WN;
    constexpr int THREADS = (BM / WM) * (TN / WN) * 32;
    constexpr int AITERS = BM * (BK / 8) / THREADS;
    constexpr int BITERS = TN * (BK / 8) / THREADS;
    constexpr int STAGES = 3;

    extern __shared__ __half smem[];
    __half* sA = smem;
    __half* sB = smem + STAGES * BM * LDS;

    const long z = blockIdx.z;
    A += (z / divA) * sA1 + (z % divA) * sA2;
    B += (z / divB) * sB1 + (z % divB) * sB2;
    if (C)  C  += (z / divC) * sC1 + (z % divC) * sC2;
    if (C2) C2 += (z / divC) * sC21 + (z % divC) * sC22;
    const int row0 = blockIdx.y * BM;
    const int col0 = blockIdx.x * TN;

    const int tid = threadIdx.x;
    const int w = tid >> 5, lane = tid & 31;
    const int wr = w / WCOLS, wc = w % WCOLS;
    const int gid = lane >> 2, tig = lane & 3;

    uint32_t sAu = (uint32_t)__cvta_generic_to_shared(sA);
    uint32_t sBu = (uint32_t)__cvta_generic_to_shared(sB);

    const int aRow = lane & 15, aCol = (lane >> 4) << 3;
    const int bRow = ((lane >> 4) << 3) + (lane & 7), bCol = ((lane >> 3) & 1) << 3;

    float acc[MT][NT][4];
#pragma unroll
    for (int mt = 0; mt < MT; mt++)
#pragma unroll
        for (int nt = 0; nt < NT; nt++)
#pragma unroll
            for (int i = 0; i < 4; i++) acc[mt][nt][i] = 0.f;

    const int nChunks = K / BK;

    auto issue = [&](int s) {
        const int buf = s % STAGES;
        const int k0 = s * BK;
#pragma unroll
        for (int i = 0; i < AITERS; i++) {
            const int idx = i * THREADS + tid;
            const int r = idx / (BK / 8), kc = (idx % (BK / 8)) * 8;
            cpa16(sAu + (uint32_t)(((buf * BM + r) * LDS + kc) * 2),
                  A + (long)(row0 + r) * lda + k0 + kc);
        }
#pragma unroll
        for (int i = 0; i < BITERS; i++) {
            const int idx = i * THREADS + tid;
            const int r = idx / (BK / 8), kc = (idx % (BK / 8)) * 8;
            cpa16(sBu + (uint32_t)(((buf * TN + r) * LDS + kc) * 2),
                  B + (long)(col0 + r) * ldb + k0 + kc);
        }
        asm volatile("cp.async.commit_group;");
    };

    issue(0);
    if (nChunks > 1) issue(1);
    for (int c = 0; c < nChunks; c++) {
        if (c + 2 < nChunks) issue(c + 2);
        const int rem = nChunks - 1 - c;
        if (rem >= 2)      asm volatile("cp.async.wait_group 2;");
        else if (rem == 1) asm volatile("cp.async.wait_group 1;");
        else               asm volatile("cp.async.wait_group 0;");
        __syncthreads();

        const int buf = c % STAGES;
        const uint32_t aBase = sAu + (uint32_t)(buf * BM * LDS * 2);
        const uint32_t bBase = sBu + (uint32_t)(buf * TN * LDS * 2);
#pragma unroll
        for (int kk = 0; kk < BK; kk += 16) {
            uint32_t af[MT][4], bfr[NT][2];
#pragma unroll
            for (int mt = 0; mt < MT; mt++) {
                const int r = wr * WM + mt * 16;
                ldsm4(af[mt][0], af[mt][1], af[mt][2], af[mt][3],
                      aBase + (uint32_t)(((r + aRow) * LDS + kk + aCol) * 2));
            }
#pragma unroll
            for (int nt = 0; nt < NT; nt += 2) {
                const int n0 = wc * WN + nt * 8;
                ldsm4(bfr[nt][0], bfr[nt][1], bfr[nt + 1][0], bfr[nt + 1][1],
                      bBase + (uint32_t)(((n0 + bRow) * LDS + kk + bCol) * 2));
            }
#pragma unroll
            for (int mt = 0; mt < MT; mt++)
#pragma unroll
                for (int nt = 0; nt < NT; nt++)
                    MMA16816(acc[mt][nt], af[mt], bfr[nt]);
        }
        __syncthreads();
    }

    // epilogue
#pragma unroll
    for (int mt = 0; mt < MT; mt++) {
#pragma unroll
        for (int nt = 0; nt < NT; nt++) {
            const int rloc = wr * WM + mt * 16 + gid;
            const int cloc = wc * WN + nt * 8 + tig * 2;
            const int cg = col0 + cloc;
            float b0 = bias ? bias[cg] : 0.f;
            float b1 = bias ? bias[cg + 1] : 0.f;
#pragma unroll
            for (int half = 0; half < 2; half++) {
                const int rg = row0 + rloc + half * 8;
                float v0 = acc[mt][nt][half * 2 + 0] * scale + b0;
                float v1 = acc[mt][nt][half * 2 + 1] * scale + b1;
                if (act == 1) { v0 = fmaxf(v0, 0.f); v1 = fmaxf(v1, 0.f); }
                else if (act == 2) {
                    v0 = (v0 > 0.f) ? v0 : expm1f(v0);
                    v1 = (v1 > 0.f) ? v1 : expm1f(v1);
                }
                if (C)
                    *reinterpret_cast<float2*>(&C[(long)rg * ldc + cg]) = make_float2(v0, v1);
                if (C2)
                    *reinterpret_cast<__half2*>(&C2[(long)rg * ldc2 + cg]) =
                        __halves2half2(__float2half_rn(v0), __float2half_rn(v1));
            }
        }
    }
}

// ---------------- fused softmax + attn@v ----------------
// probsOut==null: single-exp path (unnormalized P, divide at end).
__global__ __launch_bounds__(128)
void softmax_av(const float* __restrict__ s, const int* __restrict__ mask,
                const __half* __restrict__ v2t,
                __half* __restrict__ o2,
                float* __restrict__ probsOut, int headBase)
{
    constexpr int LDA = 72;
    constexpr int LDB = 520;
    extern __shared__ __half dsm[];
    __half* vbuf = dsm;
    __half* pbuf = dsm + 32 * LDB;
    __shared__ float rowm[64], rowinv[64];

    const int zz = blockIdx.z;
    const int g = headBase + zz;
    const int q0 = blockIdx.x * 64;
    const int mb = (g >> 3) * CN;
    const float* sbase = s + (long)zz * CN * CN;
    float* pout = probsOut ? probsOut + (long)zz * CN * CN : nullptr;
    const __half* vb = v2t + (long)g * 32 * 512;
    o2 += (long)(g >> 3) * ((long)CN * 256) + (g & 7) * 32;

    const int tid = threadIdx.x;
    const int w = tid >> 5, lane = tid & 31;
    const int gid = lane >> 2, tig = lane & 3;

    uint32_t vbu = (uint32_t)__cvta_generic_to_shared(vbuf);
    uint32_t pbu = (uint32_t)__cvta_generic_to_shared(pbuf);

#pragma unroll
    for (int i = 0; i < 16; i++) {
        const int idx = i * 128 + tid;
        const int r = idx >> 6, ch = idx & 63;
        cpa16(vbu + (uint32_t)((r * LDB + ch * 8) * 2), vb + r * 512 + ch * 8);
    }
    asm volatile("cp.async.commit_group;");

    // pass 1: per-row max (and sum only when exact probs are required)
    for (int i = 0; i < 16; i++) {
        const int r = w * 16 + i;
        const float* srow = sbase + (long)(q0 + r) * CN;
        float mx = -1e30f;
        for (int j = lane; j < CN; j += 32)
            mx = fmaxf(mx, srow[j] + (float)mask[mb + j] * NEG_INF_F);
#pragma unroll
        for (int off = 16; off > 0; off >>= 1)
            mx = fmaxf(mx, __shfl_xor_sync(0xffffffffu, mx, off));
        if (pout) {
            float sum = 0.f;
            for (int j = lane; j < CN; j += 32)
                sum += __expf(srow[j] + (float)mask[mb + j] * NEG_INF_F - mx);
#pragma unroll
            for (int off = 16; off > 0; off >>= 1)
                sum += __shfl_xor_sync(0xffffffffu, sum, off);
            if (lane == 0) rowinv[r] = 1.f / sum;
        }
        if (lane == 0) rowm[r] = mx;
    }
    asm volatile("cp.async.wait_group 0;");
    __syncthreads();

    const int aRow = lane & 15, aCol = (lane >> 4) << 3;
    const int bRow = ((lane >> 4) << 3) + (lane & 7), bCol = ((lane >> 3) & 1) << 3;

    float acc[4][4];
#pragma unroll
    for (int nt = 0; nt < 4; nt++)
#pragma unroll
        for (int i = 0; i < 4; i++) acc[nt][i] = 0.f;
    float sums[16];
#pragma unroll
    for (int i = 0; i < 16; i++) sums[i] = 0.f;

    for (int jc = 0; jc < 8; jc++) {
#pragma unroll
        for (int i = 0; i < 16; i++) {
            const int r = w * 16 + i;
            const int j = jc * 64 + lane * 2;
            const float* sp = sbase + (long)(q0 + r) * CN + j;
            float2 v2 = *reinterpret_cast<const float2*>(sp);
            const float m = rowm[r];
            float p0 = __expf(v2.x + (float)mask[mb + j] * NEG_INF_F - m);
            float p1 = __expf(v2.y + (float)mask[mb + j + 1] * NEG_INF_F - m);
            if (pout) {
                const float inv = rowinv[r];
                p0 *= inv; p1 *= inv;
                *reinterpret_cast<float2*>(&pout[(long)(q0 + r) * CN + j]) = make_float2(p0, p1);
            } else {
                sums[i] += p0 + p1;
            }
            *reinterpret_cast<__half2*>(&pbuf[r * LDA + lane * 2]) =
                __halves2half2(__float2half_rn(p0), __float2half_rn(p1));
        }
        __syncwarp();
#pragma unroll
        for (int kk = 0; kk < 64; kk += 16) {
            uint32_t af[4];
            ldsm4(af[0], af[1], af[2], af[3],
                  pbu + (uint32_t)(((w * 16 + aRow) * LDA + kk + aCol) * 2));
            uint32_t bfr[4][2];
#pragma unroll
            for (int nt = 0; nt < 4; nt += 2) {
                const int n0 = nt * 8;
                ldsm4(bfr[nt][0], bfr[nt][1], bfr[nt + 1][0], bfr[nt + 1][1],
                      vbu + (uint32_t)(((n0 + bRow) * LDB + jc * 64 + kk + bCol) * 2));
            }
#pragma unroll
            for (int nt = 0; nt < 4; nt++)
                MMA16816(acc[nt], af, bfr[nt]);
        }
        __syncwarp();
    }

    float inv0 = 1.f, inv1 = 1.f;
    if (!pout) {
#pragma unroll
        for (int i = 0; i < 16; i++) {
            float sm = sums[i];
#pragma unroll
            for (int off = 16; off > 0; off >>= 1)
                sm += __shfl_xor_sync(0xffffffffu, sm, off);
            if (lane == 0) rowinv[w * 16 + i] = 1.f / sm;
        }
        __syncwarp();
        inv0 = rowinv[w * 16 + gid];
        inv1 = rowinv[w * 16 + gid + 8];
    }

#pragma unroll
    for (int nt = 0; nt < 4; nt++) {
        const int cg = nt * 8 + tig * 2;
#pragma unroll
        for (int half = 0; half < 2; half++) {
            const int rg = q0 + w * 16 + gid + half * 8;
            const float sc = half ? inv1 : inv0;
            *reinterpret_cast<__half2*>(&o2[(long)rg * 256 + cg]) =
                __halves2half2(__float2half_rn(acc[nt][half * 2 + 0] * sc),
                               __float2half_rn(acc[nt][half * 2 + 1] * sc));
        }
    }
}

// ---------------- fused weight convert ----------------
struct WEnt { const float* src; __half* dst; int R; int C; int tiles; };
struct WTab { WEnt e[13]; };

__global__ void wsplit_all(WTab tab)
{
    __shared__ float tile[128][33];
    int bid = blockIdx.x;
    int i = 0;
    while (bid >= tab.e[i].tiles) { bid -= tab.e[i].tiles; i++; }
    const float* in = tab.e[i].src;
    __half* out = tab.e[i].dst;
    const int R = tab.e[i].R, C = tab.e[i].C;
    const int tC = C >> 5;
    const int r0 = (bid / tC) * 128, c0 = (bid % tC) * 32;

    for (int t = threadIdx.x; t < 128 * 32; t += 256) {
        int rr = t >> 5, cc = t & 31;
        tile[rr][cc] = in[(long)(r0 + rr) * C + c0 + cc];
    }
    __syncthreads();
    for (int t = threadIdx.x; t < 32 * 128; t += 256) {
        int cc = t >> 7, rr = t & 127;
        out[(long)(c0 + cc) * R + (r0 + rr)] = __float2half_rn(tile[rr][cc]);
    }
}

__global__ void pack_bias(const float* __restrict__ bq, const float* __restrict__ bk,
                          const float* __restrict__ bv, float* __restrict__ dst)
{
    const int l = blockIdx.x;
    const int d = threadIdx.x;
    float v;
    if (d < 256) v = bq[l * 256 + d];
    else if (d < 512) v = bk[l * 256 + d - 256];
    else v = bv[l * 256 + d - 512];
    dst[l * 768 + d] = v;
}

// ---------------- elementwise kernels ----------------

__global__ void embed_kernel(const int* __restrict__ node, const float* __restrict__ embed,
                             float* __restrict__ x, __half* __restrict__ x2)
{
    const int row = blockIdx.x;
    const int d = threadIdx.x;
    const float v = embed[(long)node[row] * CD + d];
    x[(long)row * CD + d] = v;
    x2[(long)row * 256 + d] = __float2half_rn(v);
}

// fp32 in [R,C] -> fp16 out [C,R]
__global__ void tsplitB(const float* __restrict__ in, __half* __restrict__ out,
                        int irs, int R, long sIn1, long sIn2, int divIn, long sOut)
{
    __shared__ float tile[128][33];
    const long z = blockIdx.z;
    in  += (z / divIn) * sIn1 + (z % divIn) * sIn2;
    out += z * sOut;
    const int r0 = blockIdx.x * 128, c0 = blockIdx.y * 32;
    for (int i = threadIdx.x; i < 128 * 32; i += 256) {
        int rr = i >> 5, cc = i & 31;
        tile[rr][cc] = in[(long)(r0 + rr) * irs + c0 + cc];
    }
    __syncthreads();
    for (int i = threadIdx.x; i < 32 * 128; i += 256) {
        int cc = i >> 7, rr = i & 127;
        out[(long)(c0 + cc) * R + (r0 + rr)] = __float2half_rn(tile[rr][cc]);
    }
}

// fp16 v slice of qkv2 -> v2t [32][512] per (b,h)
__global__ void tsplitH(const __half* __restrict__ qkv2, __half* __restrict__ out)
{
    __shared__ __half tile[128][34];
    const int z = blockIdx.z;
    const __half* in = qkv2 + (long)(z >> 3) * (512 * 768) + 512 + (z & 7) * 32;
    out += (long)z * 32 * 512;
    const int r0 = blockIdx.x * 128;
    for (int i = threadIdx.x; i < 128 * 32; i += 256) {
        int rr = i >> 5, cc = i & 31;
        tile[rr][cc] = in[(long)(r0 + rr) * 768 + cc];
    }
    __syncthreads();
    for (int i = threadIdx.x; i < 32 * 128; i += 256) {
        int cc = i >> 7, rr = i & 127;
        out[(long)cc * 512 + r0 + rr] = tile[rr][cc];
    }
}

__global__ void e12_kernel(const float* __restrict__ h, const float* __restrict__ a1,
                           const float* __restrict__ a2, float* __restrict__ e1, float* __restrict__ e2)
{
    const int row = blockIdx.x;
    const int d = threadIdx.x;
    __shared__ float s1[256], s2[256];
    const float hv = h[(long)row * CD + d];
    s1[d] = hv * a1[d];
    s2[d] = hv * a2[d];
    __syncthreads();
    for (int off = 128; off > 0; off >>= 1) {
        if (d < off) { s1[d] += s1[d + off]; s2[d] += s2[d + off]; }
        __syncthreads();
    }
    if (d == 0) { e1[row] = s1[0]; e2[row] = s2[0]; }
}

__global__ void gat_softmax_kernel(const float* __restrict__ e1, const float* __restrict__ e2,
                                   const int* __restrict__ edge, __half* __restrict__ al2)
{
    const int row = blockIdx.x;
    const int b = row / CN;
    const int t = threadIdx.x;
    __shared__ float red[256];
    const float ei = e1[row];
    float vals[2];
#pragma unroll
    for (int p = 0; p < 2; p++) {
        const int j = t + p * 256;
        float e = ei + e2[b * CN + j];
        e = (e >= 0.f) ? e : 0.2f * e;
        vals[p] = (edge[(long)row * CN + j] > 0) ? e : NEG_INF_F;
    }
    red[t] = fmaxf(vals[0], vals[1]);
    __syncthreads();
    for (int off = 128; off > 0; off >>= 1) { if (t < off) red[t] = fmaxf(red[t], red[t + off]); __syncthreads(); }
    const float m = red[0];
    __syncthreads();
    float ex[2] = {__expf(vals[0] - m), __expf(vals[1] - m)};
    red[t] = ex[0] + ex[1];
    __syncthreads();
    for (int off = 128; off > 0; off >>= 1) { if (t < off) red[t] += red[t + off]; __syncthreads(); }
    const float inv = 1.f / red[0];
    const long b2 = (long)row * 512;
#pragma unroll
    for (int p = 0; p < 2; p++) {
        const int j = t + p * 256;
        al2[b2 + j] = __float2half_rn(ex[p] * inv);
    }
}

__global__ void scale_pe_kernel(float* __restrict__ x, __half* __restrict__ x2)
{
    const int row = blockIdx.x;
    const int n = row % CN;
    const int d = threadIdx.x;
    const float expo = (2.0f * (float)(d >> 1)) / (float)CD;
    const float angle = (float)n * powf(10000.0f, -expo);
    const float pe = (d & 1) ? cosf(angle) : sinf(angle);
    const long idx = (long)row * CD + d;
    const float v = x[idx] * 16.0f + pe;
    x[idx] = v;
    x2[(long)row * 256 + d] = __float2half_rn(v);
}

__global__ void ln_kernel(const float* __restrict__ x, const float* __restrict__ delta,
                          const float* __restrict__ g, const float* __restrict__ bb,
                          float* __restrict__ out, __half* __restrict__ x2)
{
    const int row = blockIdx.x;
    const int d = threadIdx.x;
    __shared__ float red[256];
    const long idx = (long)row * CD + d;
    const float v = x[idx] + delta[idx];
    red[d] = v;
    __syncthreads();
    for (int off = 128; off > 0; off >>= 1) { if (d < off) red[d] += red[d + off]; __syncthreads(); }
    const float mu = red[0] * (1.0f / CD);
    __syncthreads();
    const float c = v - mu;
    red[d] = c * c;
    __syncthreads();
    for (int off = 128; off > 0; off >>= 1) { if (d < off) red[d] += red[d + off]; __syncthreads(); }
    const float var = red[0] * (1.0f / CD);
    const float r = c * rsqrtf(var + 1e-6f) * g[d] + bb[d];
    out[idx] = r;
    if (x2) x2[(long)row * 256 + d] = __float2half_rn(r);
}

// ---------------- host ----------------
struct G2 { __half* p; long s1; long s2; int ld; };
struct BO { long s1; long s2; int divv; };

static void launch_gemm64(const __half* A, const __half* B, const float* bias, float* C,
                          int M, int N, int K, int lda, int ldb, int ldc,
                          BO bA, BO bB, long sC1, long sC2, int divC,
                          float scale, int act, int batch, G2 g2)
{
    dim3 g(N / 64, M / 64, batch);
    size_t sm = 3 * (64 + 64) * 72 * 2;
    gemm_mma<64, 64, 64><<<g, 128, sm>>>(A, B, bias, C, lda, ldb, ldc, K,
        bA.s1, bA.s2, bA.divv, bB.s1, bB.s2, bB.divv, sC1, sC2, divC,
        scale, act, g2.p, g2.s1, g2.s2, g2.ld);
}
static void launch_gemm32(const __half* A, const __half* B, float* C,
                          int M, int N, int K, int lda, int ldb, int ldc,
                          BO bA, BO bB, long sC1, float scale, int batch)
{
    dim3 g(N / 64, M / 64, batch);
    size_t sm = 3 * (64 + 64) * 40 * 2;
    gemm_mma<64, 64, 32><<<g, 128, sm>>>(A, B, nullptr, C, lda, ldb, ldc, K,
        bA.s1, bA.s2, bA.divv, bB.s1, bB.s2, bB.divv, sC1, 0, 1,
        scale, 0, nullptr, 0, 0, 0);
}

extern "C" void kernel_launch(void* const* d_in, const int* in_sizes, int n_in,
                              void* d_out, int out_size)
{
    const int*   node  = (const int*)  d_in[0];
    const int*   edge  = (const int*)  d_in[1];
    const int*   mask  = (const int*)  d_in[2];
    const float* embed = (const float*)d_in[4];
    const float* Wg    = (const float*)d_in[5];
    const float* a1    = (const float*)d_in[6];
    const float* a2    = (const float*)d_in[7];
    const float* Wq    = (const float*)d_in[8];
    const float* bq    = (const float*)d_in[9];
    const float* Wk    = (const float*)d_in[10];
    const float* bk    = (const float*)d_in[11];
    const float* Wv    = (const float*)d_in[12];
    const float* bv    = (const float*)d_in[13];
    const float* Wo    = (const float*)d_in[14];
    const float* bo    = (const float*)d_in[15];
    const float* W1    = (const float*)d_in[16];
    const float* b1    = (const float*)d_in[17];
    const float* W2    = (const float*)d_in[18];
    const float* b2    = (const float*)d_in[19];
    const float* ln1g  = (const float*)d_in[20];
    const float* ln1b  = (const float*)d_in[21];
    const float* ln2g  = (const float*)d_in[22];
    const float* ln2b  = (const float*)d_in[23];

    cudaFuncSetAttribute((const void*)gemm_mma<64,64,64>, cudaFuncAttributeMaxDynamicSharedMemorySize, 60000);
    cudaFuncSetAttribute((const void*)gemm_mma<64,64,32>, cudaFuncAttributeMaxDynamicSharedMemorySize, 40000);
    cudaFuncSetAttribute((const void*)softmax_av, cudaFuncAttributeMaxDynamicSharedMemorySize, 50000);

    float *x, *h, *t, *e1, *e2, *bias3, *sc;
    __half *qkv2, *x2, *o2, *ff2, *h2t, *al2, *v2t;
    __half *wg2, *wqkv2, *wo2, *w12, *w22;
    cudaGetSymbolAddress((void**)&x, g_x);     cudaGetSymbolAddress((void**)&h, g_h);
    cudaGetSymbolAddress((void**)&t, g_t);
    cudaGetSymbolAddress((void**)&e1, g_e1);   cudaGetSymbolAddress((void**)&e2, g_e2);
    cudaGetSymbolAddress((void**)&bias3, g_bias);
    cudaGetSymbolAddress((void**)&sc, g_sc);
    cudaGetSymbolAddress((void**)&qkv2, g_qkv2);
    cudaGetSymbolAddress((void**)&x2, g_x2);   cudaGetSymbolAddress((void**)&o2, g_o2);
    cudaGetSymbolAddress((void**)&ff2, g_ff2); cudaGetSymbolAddress((void**)&h2t, g_h2t);
    cudaGetSymbolAddress((void**)&al2, g_al2);
    cudaGetSymbolAddress((void**)&v2t, g_v2t);
    cudaGetSymbolAddress((void**)&wg2, g_wg2); cudaGetSymbolAddress((void**)&wqkv2, g_wqkv2);
    cudaGetSymbolAddress((void**)&wo2, g_wo2); cudaGetSymbolAddress((void**)&w12, g_w12);
    cudaGetSymbolAddress((void**)&w22, g_w22);

    float* out_x    = (float*)d_out;
    float* out_attn = (float*)d_out + (long)CB * CN * CD;

    const int M = CB * CN;
    const long ND = (long)CN * CD;
    const float inv_sqrt_dh = 0.17677669529663687f;
    const G2 no2 = {nullptr, 0, 0, 0};
    const BO b0 = {0, 0, 1};

    WTab tab;
    int nTiles = 0;
    auto add = [&](int i, const float* src, __half* dst, int R, int C) {
        tab.e[i] = {src, dst, R, C, (R / 128) * (C / 32)};
        nTiles += tab.e[i].tiles;
    };
    add(0, Wg, wg2, 256, 256);
    for (int l = 0; l < CL; l++) {
        const long w256 = (long)l * 65536, w1k = (long)l * 262144;
        add(1 + l * 6, Wq + w256, wqkv2 + (long)l * 768 * 256, 256, 256);
        add(2 + l * 6, Wk + w256, wqkv2 + (long)l * 768 * 256 + 256 * 256, 256, 256);
        add(3 + l * 6, Wv + w256, wqkv2 + (long)l * 768 * 256 + 512 * 256, 256, 256);
        add(4 + l * 6, Wo + w256, wo2 + (long)l * 256 * 256, 256, 256);
        add(5 + l * 6, W1 + w1k, w12 + (long)l * 1024 * 256, 256, 1024);
        add(6 + l * 6, W2 + w1k, w22 + (long)l * 256 * 1024, 1024, 256);
    }
    wsplit_all<<<nTiles, 256>>>(tab);
    pack_bias<<<CL, 768>>>(bq, bk, bv, bias3);

    embed_kernel<<<M, CD>>>(node, embed, x, x2);

    for (int hop = 0; hop < 2; hop++) {
        launch_gemm64(x2, wg2, nullptr, h, M, CD, 256, 256, 256, CD,
                      b0, b0, 0, 0, 1, 1.f, 0, 1, no2);
        tsplitB<<<dim3(4, 8, CB), 256>>>(h, h2t, CD, CN, ND, 0, 1, (long)CD * 512);
        e12_kernel<<<M, CD>>>(h, a1, a2, e1, e2);
        gat_softmax_kernel<<<M, 256>>>(e1, e2, edge, al2);
        G2 gx2 = {x2, (long)CN * 256, 0, 256};
        BO bAa = {(long)CN * 512, 0, 1};
        BO bBh = {(long)CD * 512, 0, 1};
        launch_gemm64(al2, h2t, nullptr, hop == 1 ? x : nullptr, CN, CD, 512,
                      512, 512, CD, bAa, bBh, ND, 0, 1, 1.f, 2, CB, gx2);
    }

    scale_pe_kernel<<<M, CD>>>(x, x2);

    for (int l = 0; l < CL; l++) {
        // QKV -> fp16 qkv2 only
        G2 gq = {qkv2, 0, 0, 768};
        launch_gemm64(x2, wqkv2 + (long)l * 768 * 256, bias3 + l * 768, nullptr,
                      M, 768, 256, 256, 256, 0,
                      b0, b0, 0, 0, 1, 1.f, 0, 1, gq);

        tsplitH<<<dim3(4, 1, CB * CH), 256>>>(qkv2, v2t);

        const bool last = (l == CL - 1);
        for (int half = 0; half < 2; half++) {
            const __half* qbase = qkv2 + (long)half * 8 * 512 * 768;
            BO bAq = {512L * 768, 32, 8};
            // scores: q/k straight from qkv2, lda/ldb=768, K=32
            launch_gemm32(qbase, qbase + 256, sc, CN, CN, 32, 768, 768, CN,
                          bAq, bAq, (long)CN * CN, inv_sqrt_dh, 64);
            softmax_av<<<dim3(8, 1, 64), 128, (32 * 520 + 64 * 72) * 2>>>(
                sc, mask, v2t, o2,
                last ? out_attn + (long)half * 64 * CN * CN : nullptr,
                half * 64);
        }

        launch_gemm64(o2, wo2 + (long)l * 256 * 256, bo + l * CD, t, M, CD, 256,
                      256, 256, CD, b0, b0, 0, 0, 1, 1.f, 0, 1, no2);
        ln_kernel<<<M, CD>>>(x, t, ln1g + l * CD, ln1b + l * CD, x, x2);

        G2 gff2 = {ff2, 0, 0, 1024};
        launch_gemm64(x2, w12 + (long)l * 1024 * 256, b1 + l * CDFF, nullptr,
                      M, CDFF, 256, 256, 256, CDFF, b0, b0, 0, 0, 1, 1.f, 1, 1, gff2);
        launch_gemm64(ff2, w22 + (long)l * 256 * 1024, b2 + l * CD, t, M, CD, 1024,
                      1024, 1024, CD, b0, b0, 0, 0, 1, 1.f, 0, 1, no2);
        ln_kernel<<<M, CD>>>(x, t, ln2g + l * CD, ln2b + l * CD,
                             last ? out_x : x, last ? nullptr : x2);
    }
}